// round 1
// baseline (speedup 1.0000x reference)
#include <cuda_runtime.h>
#include <math.h>

// Problem constants
#define Bz    128
#define Tt    1024
#define Dd    512
#define Hh    512
#define Oo    256
#define G4H   2048
#define GKb   8
#define FEAT  4608      // H + H*GK
#define NBLK  148
#define NTHR  256
#define KSPLIT 4
#define KCH   1152      // FEAT / KSPLIT

// ---------------- device scratch (static: no allocations allowed) ----------------
__device__ float g_xw0[(size_t)Tt * Bz * G4H];   // 1 GiB: precomputed x@wih0^T + bih0 + bhh0, row = t*128+b
__device__ float g_W2[(size_t)2 * Hh * FEAT];    // per-layer [base | spline*scaler] weights, row-major (o, 4608)
__device__ float g_Wg1[(size_t)G4H * 1024];      // layer-1 concat [wih1 | whh1], row-major (n, 1024)
__device__ float g_bg1[G4H];                     // bih1 + bhh1
__device__ float g_hcat[Bz * 1024];              // [h0 | h1] per batch row
__device__ float g_c[2 * Bz * Hh];               // cell states
__device__ float g_sig[Bz * G4H];                // sigmoided i/f/o gates (g slot unused)
__device__ float g_feat[(size_t)Bz * FEAT];      // [silu(g) | spline bases]
__device__ float g_part[KSPLIT * Bz * Hh];       // K-split partial sums of KAN matmul
__device__ float g_invd[Hh * 30];                // reciprocal knot denominators per feature
__device__ unsigned g_bar;

// ---------------- grid-wide barrier (all 148 blocks resident) ----------------
__device__ __forceinline__ void gsync(unsigned target) {
    __syncthreads();
    if (threadIdx.x == 0) {
        __threadfence();                       // publish our writes (also orders)
        atomicAdd(&g_bar, 1u);
        while (*((volatile unsigned*)&g_bar) < target) { }
        __threadfence();                       // gpu-scope fence -> CCTL.IVALL flushes L1
    }
    __syncthreads();
}

// ---------------- init: build derived weights, zero states ----------------
__global__ void init_kernel(const float* __restrict__ wih, const float* __restrict__ whh,
                            const float* __restrict__ bih, const float* __restrict__ bhh,
                            const float* __restrict__ kbase, const float* __restrict__ kspl,
                            const float* __restrict__ kscl, const float* __restrict__ grid)
{
    size_t stride = (size_t)gridDim.x * blockDim.x;
    size_t t0 = (size_t)blockIdx.x * blockDim.x + threadIdx.x;

    // W2[l][o][k]: k<512 -> base weight; else spline*scaler flattened (i,g)
    for (size_t idx = t0; idx < (size_t)2 * Hh * FEAT; idx += stride) {
        int l = (int)(idx / ((size_t)Hh * FEAT));
        int rem = (int)(idx % ((size_t)Hh * FEAT));
        int o = rem / FEAT, k = rem % FEAT;
        int lo = l * Hh + o;
        float v;
        if (k < Hh) {
            v = kbase[(size_t)lo * Hh + k];
        } else {
            int j = k - Hh;
            int i = j >> 3, gg = j & 7;
            v = kspl[((size_t)lo * Hh + i) * GKb + gg] * kscl[(size_t)lo * Hh + i];
        }
        g_W2[idx] = v;
    }
    // Wg1[n][k]: [wih1 | whh1]
    for (size_t idx = t0; idx < (size_t)G4H * 1024; idx += stride) {
        int n = (int)(idx >> 10), k = (int)(idx & 1023);
        g_Wg1[idx] = (k < Hh) ? wih[(size_t)G4H * Dd + (size_t)n * Dd + k]
                              : whh[(size_t)G4H * Hh + (size_t)n * Hh + (k - Hh)];
    }
    for (size_t idx = t0; idx < G4H; idx += stride)
        g_bg1[idx] = bih[G4H + idx] + bhh[G4H + idx];
    for (size_t idx = t0; idx < (size_t)Bz * 1024; idx += stride) g_hcat[idx] = 0.f;
    for (size_t idx = t0; idx < (size_t)2 * Bz * Hh; idx += stride) g_c[idx] = 0.f;
    // reciprocal denominators: k=1 -> 11 entries at 0, k=2 -> 10 at 11, k=3 -> 9 at 21
    for (size_t idx = t0; idx < (size_t)Hh * 30; idx += stride) {
        int i = (int)(idx / 30), j = (int)(idx % 30);
        int k, jj;
        if (j < 11)      { k = 1; jj = j; }
        else if (j < 21) { k = 2; jj = j - 11; }
        else             { k = 3; jj = j - 21; }
        g_invd[idx] = 1.0f / (grid[i * 12 + jj + k] - grid[i * 12 + jj]);
    }
    if (t0 == 0) g_bar = 0u;
}

// ---------------- precompute: g_xw0 = x @ wih0^T + bih0 + bhh0 ----------------
// M = T*B (row = t*128 + b), N = 2048, K = 512. 64x64 tiles, 4x4 microtile.
__global__ void __launch_bounds__(NTHR) xw0_gemm(const float* __restrict__ x,
                                                 const float* __restrict__ wih,
                                                 const float* __restrict__ bih,
                                                 const float* __restrict__ bhh)
{
    __shared__ float sA[16 * 65];
    __shared__ float sB[16 * 65];
    int tid = threadIdx.x;
    int tx = tid & 15, ty = tid >> 4;
    int n0 = blockIdx.x * 64;
    int m0 = blockIdx.y * 64;
    float acc[4][4] = {};

    int lr = tid >> 2;          // 0..63
    int lc = (tid & 3) * 4;     // 0,4,8,12
    int row = m0 + lr;          // row = t*128 + b
    const float* xrow = x + ((size_t)(row & 127) * Tt + (size_t)(row >> 7)) * Dd;
    const float* wrow = wih + (size_t)(n0 + lr) * Dd;

    for (int kb = 0; kb < Dd; kb += 16) {
        __syncthreads();
        float4 a = *(const float4*)(xrow + kb + lc);
        sA[(lc + 0) * 65 + lr] = a.x; sA[(lc + 1) * 65 + lr] = a.y;
        sA[(lc + 2) * 65 + lr] = a.z; sA[(lc + 3) * 65 + lr] = a.w;
        float4 w = *(const float4*)(wrow + kb + lc);
        sB[(lc + 0) * 65 + lr] = w.x; sB[(lc + 1) * 65 + lr] = w.y;
        sB[(lc + 2) * 65 + lr] = w.z; sB[(lc + 3) * 65 + lr] = w.w;
        __syncthreads();
#pragma unroll
        for (int k = 0; k < 16; k++) {
            float a0 = sA[k * 65 + ty * 4 + 0];
            float a1 = sA[k * 65 + ty * 4 + 1];
            float a2 = sA[k * 65 + ty * 4 + 2];
            float a3 = sA[k * 65 + ty * 4 + 3];
            float b0 = sB[k * 65 + tx * 4 + 0];
            float b1 = sB[k * 65 + tx * 4 + 1];
            float b2 = sB[k * 65 + tx * 4 + 2];
            float b3 = sB[k * 65 + tx * 4 + 3];
            acc[0][0] += a0 * b0; acc[0][1] += a0 * b1; acc[0][2] += a0 * b2; acc[0][3] += a0 * b3;
            acc[1][0] += a1 * b0; acc[1][1] += a1 * b1; acc[1][2] += a1 * b2; acc[1][3] += a1 * b3;
            acc[2][0] += a2 * b0; acc[2][1] += a2 * b1; acc[2][2] += a2 * b2; acc[2][3] += a2 * b3;
            acc[3][0] += a3 * b0; acc[3][1] += a3 * b1; acc[3][2] += a3 * b2; acc[3][3] += a3 * b3;
        }
    }
#pragma unroll
    for (int i = 0; i < 4; i++) {
        int r = m0 + ty * 4 + i;
#pragma unroll
        for (int j = 0; j < 4; j++) {
            int n = n0 + tx * 4 + j;
            g_xw0[(size_t)r * G4H + n] = acc[i][j] + bih[n] + bhh[n];
        }
    }
}

// ---------------- 64x32 tile matmul helper (NT: out = A(64xK) * W(32xK)^T) ----------------
__device__ __forceinline__ void mm64x32(const float* __restrict__ A, int lda,
                                        const float* __restrict__ W, int ldw,
                                        int m0, int n0, int kbeg, int nchunks,
                                        float acc[4][2], float* sA, float* sB)
{
    int tid = threadIdx.x;
    int tx = tid & 15, ty = tid >> 4;
    int lr = tid >> 3;          // 0..31
    int lc = (tid & 7) * 4;     // 0,4,...,28
    for (int cc = 0; cc < nchunks; cc++) {
        int kb = kbeg + cc * 32;
        __syncthreads();
#pragma unroll
        for (int rr = 0; rr < 64; rr += 32) {
            float4 v = *(const float4*)(A + (size_t)(m0 + lr + rr) * lda + kb + lc);
            sA[(lc + 0) * 65 + lr + rr] = v.x; sA[(lc + 1) * 65 + lr + rr] = v.y;
            sA[(lc + 2) * 65 + lr + rr] = v.z; sA[(lc + 3) * 65 + lr + rr] = v.w;
        }
        {
            float4 v = *(const float4*)(W + (size_t)(n0 + lr) * ldw + kb + lc);
            sB[(lc + 0) * 33 + lr] = v.x; sB[(lc + 1) * 33 + lr] = v.y;
            sB[(lc + 2) * 33 + lr] = v.z; sB[(lc + 3) * 33 + lr] = v.w;
        }
        __syncthreads();
#pragma unroll
        for (int k = 0; k < 32; k++) {
            float a0 = sA[k * 65 + ty * 4 + 0];
            float a1 = sA[k * 65 + ty * 4 + 1];
            float a2 = sA[k * 65 + ty * 4 + 2];
            float a3 = sA[k * 65 + ty * 4 + 3];
            float b0 = sB[k * 33 + tx * 2 + 0];
            float b1 = sB[k * 33 + tx * 2 + 1];
            acc[0][0] += a0 * b0; acc[0][1] += a0 * b1;
            acc[1][0] += a1 * b0; acc[1][1] += a1 * b1;
            acc[2][0] += a2 * b0; acc[2][1] += a2 * b1;
            acc[3][0] += a3 * b0; acc[3][1] += a3 * b1;
        }
    }
}

// ---------------- persistent sequential kernel ----------------
__global__ void __launch_bounds__(NTHR, 1) persist_kernel(
    const float* __restrict__ whh, const float* __restrict__ grid,
    const float* __restrict__ fc_w, const float* __restrict__ fc_b,
    float* __restrict__ out)
{
    __shared__ float sA[32 * 65];
    __shared__ float sB[32 * 33];
    unsigned nb = 0;
    int bid = blockIdx.x, tid = threadIdx.x;
    int tx = tid & 15, ty = tid >> 4;

    for (int t = 0; t < Tt; t++) {
#pragma unroll 1
        for (int l = 0; l < 2; l++) {
            // ---- gates GEMM + elementwise epilogue ----
            if (bid < 128) {
                int m0 = (bid >> 6) * 64;
                int n0 = (bid & 63) * 32;
                float acc[4][2] = {};
                if (l == 0) mm64x32(g_hcat, 1024, whh,   Hh,   m0, n0, 0, 16, acc, sA, sB);
                else        mm64x32(g_hcat, 1024, g_Wg1, 1024, m0, n0, 0, 32, acc, sA, sB);
                int cls = n0 >> 9;   // 0:i 1:f 2:g 3:o (tile-uniform)
#pragma unroll
                for (int i = 0; i < 4; i++) {
                    int b = m0 + ty * 4 + i;
#pragma unroll
                    for (int j = 0; j < 2; j++) {
                        int n = n0 + tx * 2 + j;
                        float pre = (l == 0) ? g_xw0[((size_t)t * Bz + b) * G4H + n] : g_bg1[n];
                        float v = acc[i][j] + pre;
                        if (cls != 2) {
                            g_sig[b * G4H + n] = 1.f / (1.f + __expf(-v));
                        } else {
                            int ii = n - 1024;
                            g_feat[(size_t)b * FEAT + ii] = v / (1.f + __expf(-v));  // silu
                            float kt[12];
#pragma unroll
                            for (int q = 0; q < 12; q++) kt[q] = __ldg(&grid[ii * 12 + q]);
                            float bas[11];
#pragma unroll
                            for (int q = 0; q < 11; q++)
                                bas[q] = (v >= kt[q] && v < kt[q + 1]) ? 1.f : 0.f;
                            const float* invd = &g_invd[ii * 30];
#pragma unroll
                            for (int k = 1; k <= 3; k++) {
                                int off = (k == 1) ? 0 : ((k == 2) ? 11 : 21);
#pragma unroll
                                for (int q = 0; q + k < 11; q++) {
                                    float lf = (v - kt[q]) * __ldg(&invd[off + q]);
                                    float rf = (kt[q + k + 1] - v) * __ldg(&invd[off + q + 1]);
                                    bas[q] = lf * bas[q] + rf * bas[q + 1];
                                }
                            }
#pragma unroll
                            for (int q = 0; q < 8; q++)
                                g_feat[(size_t)b * FEAT + Hh + ii * 8 + q] = bas[q];
                        }
                    }
                }
            }
            gsync(++nb * NBLK);

            // ---- KAN GEMM (base+spline fused, K-split x4) ----
            if (bid < 128) {
                int si = bid >> 5;
                int m0 = ((bid >> 4) & 1) * 64;
                int n0 = (bid & 15) * 32;
                float acc[4][2] = {};
                mm64x32(g_feat, FEAT, g_W2 + (size_t)l * Hh * FEAT, FEAT,
                        m0, n0, si * KCH, KCH / 32, acc, sA, sB);
#pragma unroll
                for (int i = 0; i < 4; i++)
#pragma unroll
                    for (int j = 0; j < 2; j++)
                        g_part[si * Bz * Hh + (m0 + ty * 4 + i) * Hh + (n0 + tx * 2 + j)] = acc[i][j];
            }
            gsync(++nb * NBLK);

            // ---- reduce partials + LSTM cell update ----
            for (int idx = bid * NTHR + tid; idx < Bz * Hh; idx += NBLK * NTHR) {
                float v = g_part[idx] + g_part[Bz * Hh + idx]
                        + g_part[2 * Bz * Hh + idx] + g_part[3 * Bz * Hh + idx];
                int b = idx >> 9, o = idx & 511;
                float ig = g_sig[b * G4H + o];
                float fg = g_sig[b * G4H + 512 + o];
                float og = g_sig[b * G4H + 1536 + o];
                float c = fg * g_c[l * Bz * Hh + idx] + ig * v;
                g_c[l * Bz * Hh + idx] = c;
                g_hcat[b * 1024 + l * 512 + o] = og * tanhf(c);
            }
            gsync(++nb * NBLK);
        }
    }

    // ---- final FC: out = h1 @ fc_w^T + fc_b ----
    for (int idx = bid * NTHR + tid; idx < Bz * Oo; idx += NBLK * NTHR) {
        int o = idx >> 7, b = idx & 127;
        float s = fc_b[o];
        const float* hp = &g_hcat[b * 1024 + 512];
        const float* wp = &fc_w[(size_t)o * Hh];
#pragma unroll 4
        for (int k = 0; k < Hh; k++) s += hp[k] * wp[k];
        out[b * Oo + o] = s;
    }
}

// ---------------- launch ----------------
extern "C" void kernel_launch(void* const* d_in, const int* in_sizes, int n_in,
                              void* d_out, int out_size)
{
    const float* x     = (const float*)d_in[0];
    const float* wih   = (const float*)d_in[1];
    const float* whh   = (const float*)d_in[2];
    const float* bih   = (const float*)d_in[3];
    const float* bhh   = (const float*)d_in[4];
    const float* kbase = (const float*)d_in[5];
    const float* kspl  = (const float*)d_in[6];
    const float* kscl  = (const float*)d_in[7];
    const float* grid  = (const float*)d_in[8];
    const float* fc_w  = (const float*)d_in[9];
    const float* fc_b  = (const float*)d_in[10];
    float* out = (float*)d_out;

    init_kernel<<<4096, NTHR>>>(wih, whh, bih, bhh, kbase, kspl, kscl, grid);
    dim3 gg(G4H / 64, (Tt * Bz) / 64);
    xw0_gemm<<<gg, NTHR>>>(x, wih, bih, bhh);
    persist_kernel<<<NBLK, NTHR>>>(whh, grid, fc_w, fc_b, out);
}

// round 2
// speedup vs baseline: 2.0277x; 2.0277x over previous
#include <cuda_runtime.h>
#include <math.h>

// Problem constants
#define Bz    128
#define Tt    1024
#define Dd    512
#define Hh    512
#define Oo    256
#define G4H   2048
#define FEAT  4608      // H + H*8
#define NBLK  128
#define NTHR  256
#define PITCH 48        // smem row pitch in floats (48 mod 32 = 16 -> conflict-light)

// ---------------- device scratch (no allocations allowed) ----------------
__device__ float g_xw0[(size_t)Tt * Bz * G4H];   // precomputed x@wih0^T + bih0 + bhh0
__device__ float g_W2[(size_t)2 * Hh * FEAT];    // [base | spline*scaler], row-major (o,4608)
__device__ float g_Wg1[(size_t)G4H * 1024];      // layer-1 concat [wih1 | whh1]
__device__ float g_bg1[G4H];
__device__ float g_hcat[Bz * 1024];              // [h0 | h1]
__device__ float g_c[2 * Bz * Hh];
__device__ float g_sig[Bz * G4H];
__device__ float g_feat[(size_t)Bz * FEAT];
__device__ float g_gp[2][Bz * G4H];              // gates K-split partials
__device__ float g_part[8][Bz * Hh];             // KAN K-split partials
__device__ float g_kt[12];                       // knot row (identical per feature)
__device__ float g_invd[30];                     // reciprocal denominators
__device__ unsigned g_bar;

// ---------------- grid barrier ----------------
__device__ __forceinline__ void gsync(unsigned target) {
    __syncthreads();
    if (threadIdx.x == 0) {
        __threadfence();
        atomicAdd(&g_bar, 1u);
        while (*((volatile unsigned*)&g_bar) < target) { }
        __threadfence();   // gpu-scope -> flush L1 so fresh data is read
    }
    __syncthreads();
}

// ---------------- tf32 helpers ----------------
__device__ __forceinline__ unsigned f2tf(float x) {
    unsigned u; asm("cvt.rna.tf32.f32 %0, %1;" : "=r"(u) : "f"(x)); return u;
}
__device__ __forceinline__ void mma8(float c[4], unsigned a0, unsigned a1, unsigned a2, unsigned a3,
                                     unsigned b0, unsigned b1) {
    asm volatile("mma.sync.aligned.m16n8k8.row.col.f32.tf32.tf32.f32 "
                 "{%0,%1,%2,%3},{%4,%5,%6,%7},{%8,%9},{%0,%1,%2,%3};"
                 : "+f"(c[0]), "+f"(c[1]), "+f"(c[2]), "+f"(c[3])
                 : "r"(a0), "r"(a1), "r"(a2), "r"(a3), "r"(b0), "r"(b1));
}

// ---------------- generic 128xNT tile GEMM: C = A(128xK) @ W(NTxK)^T ----------------
// Warps: 4 (m) x 2 (n); warp tile m32 x NT/2. K consumed in chunks of 32.
// SMEM stores fragment-permuted tf32 so fragment loads are single LDS.128.
template<int NT>
__device__ __forceinline__ void mma_tile(const float* __restrict__ A, size_t lda,
                                         const float* __restrict__ W, size_t ldw,
                                         int kbeg, int nch,
                                         float* sA, float* sB,
                                         float cacc[2][NT / 16][4])
{
    constexpr int NFR = NT / 16;   // n8 frags per warp
    constexpr int BF4 = NT / 32;   // B float4s per thread per chunk
    int tid = threadIdx.x, lane = tid & 31, warp = tid >> 5;
    int wm = (warp & 3) * 32, wn = (warp >> 2) * (NT / 2);
    int qr = lane >> 2, qc = lane & 3;
    float4 ra[4], rb[BF4];

    // prefetch chunk 0
    {
        int kb = kbeg;
#pragma unroll
        for (int j = 0; j < 4; j++) { int idx = j * 256 + tid;
            ra[j] = *(const float4*)(A + (size_t)(idx >> 3) * lda + kb + ((idx & 7) << 2)); }
#pragma unroll
        for (int j = 0; j < BF4; j++) { int idx = j * 256 + tid;
            rb[j] = *(const float4*)(W + (size_t)(idx >> 3) * ldw + kb + ((idx & 7) << 2)); }
    }
    for (int cc = 0; cc < nch; cc++) {
        __syncthreads();
        // stage regs -> smem (permuted, tf32-rounded)
#pragma unroll
        for (int j = 0; j < 4; j++) {
            int idx = j * 256 + tid; int row = idx >> 3; int c0 = (idx & 7) << 2;
            int base = row * PITCH + ((c0 >> 4) << 4) + ((c0 & 15) >> 2);
            sA[base + 0]  = __uint_as_float(f2tf(ra[j].x));
            sA[base + 4]  = __uint_as_float(f2tf(ra[j].y));
            sA[base + 8]  = __uint_as_float(f2tf(ra[j].z));
            sA[base + 12] = __uint_as_float(f2tf(ra[j].w));
        }
#pragma unroll
        for (int j = 0; j < BF4; j++) {
            int idx = j * 256 + tid; int row = idx >> 3; int c0 = (idx & 7) << 2;
            int base = row * PITCH + ((c0 >> 4) << 4) + ((c0 & 15) >> 2);
            sB[base + 0]  = __uint_as_float(f2tf(rb[j].x));
            sB[base + 4]  = __uint_as_float(f2tf(rb[j].y));
            sB[base + 8]  = __uint_as_float(f2tf(rb[j].z));
            sB[base + 12] = __uint_as_float(f2tf(rb[j].w));
        }
        __syncthreads();
        // prefetch next chunk (latency overlaps compute below)
        if (cc + 1 < nch) {
            int kb = kbeg + (cc + 1) * 32;
#pragma unroll
            for (int j = 0; j < 4; j++) { int idx = j * 256 + tid;
                ra[j] = *(const float4*)(A + (size_t)(idx >> 3) * lda + kb + ((idx & 7) << 2)); }
#pragma unroll
            for (int j = 0; j < BF4; j++) { int idx = j * 256 + tid;
                rb[j] = *(const float4*)(W + (size_t)(idx >> 3) * ldw + kb + ((idx & 7) << 2)); }
        }
        // compute: 2 k16 halves per chunk, 2 k-steps per half
#pragma unroll
        for (int h = 0; h < 2; h++) {
            unsigned bf[NFR][4];
#pragma unroll
            for (int f = 0; f < NFR; f++) {
                float4 v = *(const float4*)(sB + (wn + f * 8 + qr) * PITCH + h * 16 + qc * 4);
                bf[f][0] = __float_as_uint(v.x); bf[f][1] = __float_as_uint(v.y);
                bf[f][2] = __float_as_uint(v.z); bf[f][3] = __float_as_uint(v.w);
            }
#pragma unroll
            for (int mi = 0; mi < 2; mi++) {
                float4 lo = *(const float4*)(sA + (wm + mi * 16 + qr) * PITCH + h * 16 + qc * 4);
                float4 hi = *(const float4*)(sA + (wm + mi * 16 + 8 + qr) * PITCH + h * 16 + qc * 4);
#pragma unroll
                for (int f = 0; f < NFR; f++) {
                    mma8(cacc[mi][f], __float_as_uint(lo.x), __float_as_uint(hi.x),
                                      __float_as_uint(lo.y), __float_as_uint(hi.y), bf[f][0], bf[f][1]);
                    mma8(cacc[mi][f], __float_as_uint(lo.z), __float_as_uint(hi.z),
                                      __float_as_uint(lo.w), __float_as_uint(hi.w), bf[f][2], bf[f][3]);
                }
            }
        }
    }
}

template<int NT>
__device__ __forceinline__ void store_frags(float* dst, int ldd, int nbase, float cacc[2][NT / 16][4]) {
    int tid = threadIdx.x, lane = tid & 31, warp = tid >> 5;
    int wm = (warp & 3) * 32, wn = (warp >> 2) * (NT / 2);
    int qr = lane >> 2, qc = lane & 3;
#pragma unroll
    for (int mi = 0; mi < 2; mi++)
#pragma unroll
        for (int f = 0; f < NT / 16; f++) {
            int r0 = wm + mi * 16 + qr;
            int cb = nbase + wn + f * 8 + qc * 2;
            *(float2*)(dst + (size_t)r0 * ldd + cb)       = make_float2(cacc[mi][f][0], cacc[mi][f][1]);
            *(float2*)(dst + (size_t)(r0 + 8) * ldd + cb) = make_float2(cacc[mi][f][2], cacc[mi][f][3]);
        }
}

// ---------------- init ----------------
__global__ void init_kernel(const float* __restrict__ wih, const float* __restrict__ whh,
                            const float* __restrict__ bih, const float* __restrict__ bhh,
                            const float* __restrict__ kbase, const float* __restrict__ kspl,
                            const float* __restrict__ kscl, const float* __restrict__ grid)
{
    size_t stride = (size_t)gridDim.x * blockDim.x;
    size_t t0 = (size_t)blockIdx.x * blockDim.x + threadIdx.x;

    for (size_t idx = t0; idx < (size_t)2 * Hh * FEAT; idx += stride) {
        int l = (int)(idx / ((size_t)Hh * FEAT));
        int rem = (int)(idx % ((size_t)Hh * FEAT));
        int o = rem / FEAT, k = rem % FEAT;
        int lo = l * Hh + o;
        float v;
        if (k < Hh) v = kbase[(size_t)lo * Hh + k];
        else {
            int j = k - Hh; int i = j >> 3, gg = j & 7;
            v = kspl[((size_t)lo * Hh + i) * 8 + gg] * kscl[(size_t)lo * Hh + i];
        }
        g_W2[idx] = v;
    }
    for (size_t idx = t0; idx < (size_t)G4H * 1024; idx += stride) {
        int n = (int)(idx >> 10), k = (int)(idx & 1023);
        g_Wg1[idx] = (k < Hh) ? wih[(size_t)G4H * Dd + (size_t)n * Dd + k]
                              : whh[(size_t)G4H * Hh + (size_t)n * Hh + (k - Hh)];
    }
    for (size_t idx = t0; idx < G4H; idx += stride) g_bg1[idx] = bih[G4H + idx] + bhh[G4H + idx];
    for (size_t idx = t0; idx < (size_t)Bz * 1024; idx += stride) g_hcat[idx] = 0.f;
    for (size_t idx = t0; idx < (size_t)2 * Bz * Hh; idx += stride) g_c[idx] = 0.f;
    for (size_t idx = t0; idx < 12; idx += stride) g_kt[idx] = grid[idx];
    for (size_t idx = t0; idx < 30; idx += stride) {
        int j = (int)idx; int k, jj;
        if (j < 11)      { k = 1; jj = j; }
        else if (j < 21) { k = 2; jj = j - 11; }
        else             { k = 3; jj = j - 21; }
        g_invd[idx] = 1.0f / (grid[jj + k] - grid[jj]);
    }
    if (t0 == 0) g_bar = 0u;
}

// ---------------- xw0 precompute (tensor cores): M=131072, N=2048, K=512 ----------------
__global__ void __launch_bounds__(NTHR) xw0_mma(const float* __restrict__ x,
                                                const float* __restrict__ wih,
                                                const float* __restrict__ bih,
                                                const float* __restrict__ bhh)
{
    __shared__ __align__(16) float sA[128 * PITCH];
    __shared__ __align__(16) float sB[64 * PITCH];
    int nt = blockIdx.x, mt = blockIdx.y;
    float cacc[2][4][4] = {};
    // A rows: b = 0..127 at fixed t = mt: x[b*T*D + mt*D + k]
    mma_tile<64>(x + (size_t)mt * Dd, (size_t)Tt * Dd,
                 wih + (size_t)nt * 64 * Dd, Dd, 0, Dd / 32, sA, sB, cacc);
    int tid = threadIdx.x, lane = tid & 31, warp = tid >> 5;
    int wm = (warp & 3) * 32, wn = (warp >> 2) * 32;
    int qr = lane >> 2, qc = lane & 3;
    size_t rowbase = (size_t)mt * 128;
#pragma unroll
    for (int mi = 0; mi < 2; mi++)
#pragma unroll
        for (int f = 0; f < 4; f++) {
            int r0 = wm + mi * 16 + qr;
            int cb = nt * 64 + wn + f * 8 + qc * 2;
            float b0 = __ldg(&bih[cb]) + __ldg(&bhh[cb]);
            float b1 = __ldg(&bih[cb + 1]) + __ldg(&bhh[cb + 1]);
            *(float2*)(g_xw0 + (rowbase + r0) * G4H + cb) =
                make_float2(cacc[mi][f][0] + b0, cacc[mi][f][1] + b1);
            *(float2*)(g_xw0 + (rowbase + r0 + 8) * G4H + cb) =
                make_float2(cacc[mi][f][2] + b0, cacc[mi][f][3] + b1);
        }
}

// ---------------- persistent sequential kernel ----------------
__global__ void __launch_bounds__(NTHR, 1) persist_kernel(
    const float* __restrict__ whh, const float* __restrict__ fc_w,
    const float* __restrict__ fc_b, float* __restrict__ out)
{
    __shared__ __align__(16) float sA[128 * PITCH];
    __shared__ __align__(16) float sB[32 * PITCH];
    unsigned nb = 0;
    int bid = blockIdx.x, tid = threadIdx.x;

    for (int t = 0; t < Tt; t++) {
#pragma unroll 1
        for (int l = 0; l < 2; l++) {
            // ---- phase 1: gates mma (K-split x2, 128 jobs) ----
            {
                int nt = bid >> 1, kh = bid & 1;
                int K = (l == 0) ? 512 : 1024;
                const float* Wb = (l == 0) ? (whh + (size_t)nt * 32 * 512)
                                           : (g_Wg1 + (size_t)nt * 32 * 1024);
                float cacc[2][2][4] = {};
                mma_tile<32>(g_hcat, 1024, Wb, K, kh * (K / 2), (K / 2) >> 5, sA, sB, cacc);
                store_frags<32>(g_gp[kh], G4H, nt * 32, cacc);
            }
            gsync(++nb * NBLK);

            // ---- phase 2: gates epilogue (sigmoid / silu + spline bases) ----
            {
                float kt[12], invd[30];
#pragma unroll
                for (int q = 0; q < 12; q++) kt[q] = g_kt[q];
#pragma unroll
                for (int q = 0; q < 30; q++) invd[q] = g_invd[q];
#pragma unroll 1
                for (int it = 0; it < 8; it++) {
                    int idx = it * 32768 + bid * 256 + tid;
                    int b = idx >> 11, n = idx & 2047;
                    float pre = (l == 0) ? g_xw0[(size_t)(t * Bz + b) * G4H + n] : g_bg1[n];
                    float v = g_gp[0][idx] + g_gp[1][idx] + pre;
                    int cls = n >> 9;
                    if (cls != 2) {
                        g_sig[idx] = 1.f / (1.f + __expf(-v));
                    } else {
                        int ii = n - 1024;
                        g_feat[(size_t)b * FEAT + ii] = v / (1.f + __expf(-v));
                        float bas[11];
#pragma unroll
                        for (int q = 0; q < 11; q++)
                            bas[q] = (v >= kt[q] && v < kt[q + 1]) ? 1.f : 0.f;
#pragma unroll
                        for (int k = 1; k <= 3; k++) {
                            int off = (k == 1) ? 0 : ((k == 2) ? 11 : 21);
#pragma unroll
                            for (int q = 0; q + k < 11; q++) {
                                float lf = (v - kt[q]) * invd[off + q];
                                float rf = (kt[q + k + 1] - v) * invd[off + q + 1];
                                bas[q] = lf * bas[q] + rf * bas[q + 1];
                            }
                        }
#pragma unroll
                        for (int q = 0; q < 8; q++)
                            g_feat[(size_t)b * FEAT + Hh + ii * 8 + q] = bas[q];
                    }
                }
            }
            gsync(++nb * NBLK);

            // ---- phase 3: KAN mma (K-split x8, 128 jobs) ----
            {
                int nt = bid >> 3, ks = bid & 7;
                float cacc[2][2][4] = {};
                mma_tile<32>(g_feat, FEAT,
                             g_W2 + (size_t)l * Hh * FEAT + (size_t)nt * 32 * FEAT, FEAT,
                             ks * 576, 18, sA, sB, cacc);
                store_frags<32>(g_part[ks], Hh, nt * 32, cacc);
            }
            gsync(++nb * NBLK);

            // ---- phase 4: reduce partials + LSTM cell update ----
            {
#pragma unroll
                for (int it = 0; it < 2; it++) {
                    int idx = it * 32768 + bid * 256 + tid;
                    float v = 0.f;
#pragma unroll
                    for (int s = 0; s < 8; s++) v += g_part[s][idx];
                    int b = idx >> 9, o = idx & 511;
                    float ig = g_sig[b * G4H + o];
                    float fg = g_sig[b * G4H + 512 + o];
                    float og = g_sig[b * G4H + 1536 + o];
                    float c = fg * g_c[l * Bz * Hh + idx] + ig * v;
                    g_c[l * Bz * Hh + idx] = c;
                    g_hcat[b * 1024 + l * 512 + o] = og * tanhf(c);
                }
            }
            gsync(++nb * NBLK);
        }
    }

    // ---- final FC: out = h1 @ fc_w^T + fc_b (one element per thread) ----
    {
        int idx = bid * NTHR + tid;           // 0..32767 == Bz*Oo
        int o = idx >> 7, b = idx & 127;
        float s = fc_b[o];
        const float* hp = &g_hcat[b * 1024 + 512];
        const float* wp = &fc_w[(size_t)o * Hh];
#pragma unroll 8
        for (int k = 0; k < Hh; k++) s += hp[k] * wp[k];
        out[b * Oo + o] = s;
    }
}

// ---------------- launch ----------------
extern "C" void kernel_launch(void* const* d_in, const int* in_sizes, int n_in,
                              void* d_out, int out_size)
{
    const float* x     = (const float*)d_in[0];
    const float* wih   = (const float*)d_in[1];
    const float* whh   = (const float*)d_in[2];
    const float* bih   = (const float*)d_in[3];
    const float* bhh   = (const float*)d_in[4];
    const float* kbase = (const float*)d_in[5];
    const float* kspl  = (const float*)d_in[6];
    const float* kscl  = (const float*)d_in[7];
    const float* grid  = (const float*)d_in[8];
    const float* fc_w  = (const float*)d_in[9];
    const float* fc_b  = (const float*)d_in[10];
    float* out = (float*)d_out;

    init_kernel<<<2048, NTHR>>>(wih, whh, bih, bhh, kbase, kspl, kscl, grid);
    dim3 gg(G4H / 64, (Tt * Bz) / 128);
    xw0_mma<<<gg, NTHR>>>(x, wih, bih, bhh);
    persist_kernel<<<NBLK, NTHR>>>(whh, fc_w, fc_b, out);
}

// round 3
// speedup vs baseline: 5.0020x; 2.4668x over previous
#include <cuda_runtime.h>
#include <cuda_bf16.h>
#include <math.h>

// Problem constants
#define Bz    128
#define Tt    1024
#define Dd    512
#define Hh    512
#define Oo    256
#define G4H   2048
#define FEAT  4608
#define NBLK  128
#define NTHR  256
#define PITCH 48        // tf32 xw0 path smem pitch (floats)

// smem layout (bytes) for persist kernel
#define WP_G0 520
#define WP_G1 1032
#define WP_K  584
#define SM_WG0 0
#define SM_WG1 33280
#define SM_WK  99328
#define SM_AST 174080
#define SM_STRIDE 10240
#define SMEM_TOTAL 215040

// ---------------- device scratch ----------------
__device__ float g_xw0[(size_t)Tt * Bz * G4H];   // x@wih0^T + bih0 + bhh0 (fp32)
__device__ float g_bg1[G4H];
__device__ __nv_bfloat16 g_hcat[Bz * 1024];      // [h0 | h1] bf16
__device__ float g_c[2 * Bz * Hh];
__device__ float g_sig[Bz * G4H];
__device__ __nv_bfloat16 g_feat[(size_t)Bz * FEAT];
__device__ float g_part[8][Bz * Hh];
__device__ float g_kt[12];
__device__ float g_invd[30];
__device__ unsigned g_bar;

// ---------------- grid barrier: release/acquire, NO L1 flush ----------------
// Safe because all mutable cross-block data is read via cp.async.cg / __ldcg (L2).
__device__ __forceinline__ void gsync(unsigned target) {
    __syncthreads();
    if (threadIdx.x == 0) {
        asm volatile("red.release.gpu.global.add.u32 [%0], 1;" :: "l"(&g_bar) : "memory");
        unsigned v;
        do {
            asm volatile("ld.acquire.gpu.global.u32 %0, [%1];" : "=r"(v) : "l"(&g_bar) : "memory");
        } while (v < target);
    }
    __syncthreads();
}

// ---------------- bf16 mma primitives ----------------
__device__ __forceinline__ void ldm_x4(unsigned &r0, unsigned &r1, unsigned &r2, unsigned &r3, unsigned addr) {
    asm volatile("ldmatrix.sync.aligned.m8n8.x4.shared.b16 {%0,%1,%2,%3}, [%4];"
                 : "=r"(r0), "=r"(r1), "=r"(r2), "=r"(r3) : "r"(addr));
}
__device__ __forceinline__ void mma16816(float c[4], unsigned a0, unsigned a1, unsigned a2, unsigned a3,
                                         unsigned b0, unsigned b1) {
    asm volatile("mma.sync.aligned.m16n8k16.row.col.f32.bf16.bf16.f32 "
                 "{%0,%1,%2,%3},{%4,%5,%6,%7},{%8,%9},{%0,%1,%2,%3};"
                 : "+f"(c[0]), "+f"(c[1]), "+f"(c[2]), "+f"(c[3])
                 : "r"(a0), "r"(a1), "r"(a2), "r"(a3), "r"(b0), "r"(b1));
}

// ---------------- mma phase: C(MTxN32) += A(MTxK) @ W(32xK)^T ----------------
// Weights resident in smem (sW, pitch wp). A streamed via 4-stage cp.async.cg.
// 8 warps as 4m x 2n: warp tile (MI*16) x 16. MT = MI*64.
template<int MI, int KCH>
__device__ __forceinline__ void mma_phase(
    const __nv_bfloat16* __restrict__ Ag, int lda, int arow0, int kbeg, int nch,
    const __nv_bfloat16* sW, int wp, __nv_bfloat16* sA, float cacc[][2][4])
{
    constexpr int AP = KCH + 8;       // A smem pitch (bf16)
    constexpr int OPR = KCH / 8;      // cp.async ops per row
    int tid = threadIdx.x, lane = tid & 31, warp = tid >> 5;
    int wm = (warp & 3) * (MI * 16), wn = (warp >> 2) * 16;
    unsigned sWa = (unsigned)__cvta_generic_to_shared(sW);
    unsigned sAa = (unsigned)__cvta_generic_to_shared(sA);

    auto issue = [&](int cc) {
        const __nv_bfloat16* gb = Ag + (size_t)arow0 * lda + kbeg + cc * KCH;
        unsigned sb = sAa + (cc & 3) * SM_STRIDE;
#pragma unroll
        for (int o = 0; o < 2; o++) {
            int idx = o * NTHR + tid;
            int r = idx / OPR, c = (idx % OPR) * 8;
            unsigned sa = sb + (unsigned)(r * AP + c) * 2u;
            const void* ga = gb + (size_t)r * lda + c;
            asm volatile("cp.async.cg.shared.global [%0], [%1], 16;" :: "r"(sa), "l"(ga) : "memory");
        }
        asm volatile("cp.async.commit_group;" ::: "memory");
    };

    for (int s = 0; s < 3; s++) {
        if (s < nch) issue(s);
        else asm volatile("cp.async.commit_group;" ::: "memory");
    }

    int a_r = (lane & 7) + ((lane >> 3) & 1) * 8;   // A ldmatrix row offset
    int a_k = ((lane >> 4) & 1) * 8;                // A ldmatrix k offset
    int b_r = wn + (lane & 7) + ((lane >> 4) & 1) * 8;
    int b_k = ((lane >> 3) & 1) * 8;
    unsigned bbase = sWa + (unsigned)(b_r * wp + b_k) * 2u;

    for (int cc = 0; cc < nch; cc++) {
        asm volatile("cp.async.wait_group 2;" ::: "memory");
        __syncthreads();
        if (cc + 3 < nch) issue(cc + 3);
        else asm volatile("cp.async.commit_group;" ::: "memory");

        unsigned sb = sAa + (cc & 3) * SM_STRIDE;
        unsigned ab[MI];
#pragma unroll
        for (int mi = 0; mi < MI; mi++)
            ab[mi] = sb + (unsigned)((wm + mi * 16 + a_r) * AP + a_k) * 2u;
#pragma unroll
        for (int ks = 0; ks < KCH / 16; ks++) {
            unsigned b0, b1, b2, b3;
            ldm_x4(b0, b1, b2, b3, bbase + (unsigned)(cc * KCH + ks * 16) * 2u);
#pragma unroll
            for (int mi = 0; mi < MI; mi++) {
                unsigned a0, a1, a2, a3;
                ldm_x4(a0, a1, a2, a3, ab[mi] + ks * 32);
                mma16816(cacc[mi][0], a0, a1, a2, a3, b0, b1);
                mma16816(cacc[mi][1], a0, a1, a2, a3, b2, b3);
            }
        }
    }
}

// ---------------- tiny init ----------------
__global__ void init_kernel(const float* __restrict__ bih, const float* __restrict__ bhh,
                            const float* __restrict__ grid)
{
    size_t stride = (size_t)gridDim.x * blockDim.x;
    size_t t0 = (size_t)blockIdx.x * blockDim.x + threadIdx.x;
    for (size_t i = t0; i < G4H; i += stride) g_bg1[i] = bih[G4H + i] + bhh[G4H + i];
    for (size_t i = t0; i < (size_t)Bz * 1024; i += stride) g_hcat[i] = __float2bfloat16(0.f);
    for (size_t i = t0; i < (size_t)2 * Bz * Hh; i += stride) g_c[i] = 0.f;
    for (size_t i = t0; i < 12; i += stride) g_kt[i] = grid[i];
    for (size_t i = t0; i < 30; i += stride) {
        int j = (int)i; int k, jj;
        if (j < 11)      { k = 1; jj = j; }
        else if (j < 21) { k = 2; jj = j - 11; }
        else             { k = 3; jj = j - 21; }
        g_invd[i] = 1.0f / (grid[jj + k] - grid[jj]);
    }
    if (t0 == 0) g_bar = 0u;
}

// ---------------- tf32 xw0 precompute (proven in R2) ----------------
__device__ __forceinline__ unsigned f2tf(float x) {
    unsigned u; asm("cvt.rna.tf32.f32 %0, %1;" : "=r"(u) : "f"(x)); return u;
}
__device__ __forceinline__ void mma8(float c[4], unsigned a0, unsigned a1, unsigned a2, unsigned a3,
                                     unsigned b0, unsigned b1) {
    asm volatile("mma.sync.aligned.m16n8k8.row.col.f32.tf32.tf32.f32 "
                 "{%0,%1,%2,%3},{%4,%5,%6,%7},{%8,%9},{%0,%1,%2,%3};"
                 : "+f"(c[0]), "+f"(c[1]), "+f"(c[2]), "+f"(c[3])
                 : "r"(a0), "r"(a1), "r"(a2), "r"(a3), "r"(b0), "r"(b1));
}
template<int NT>
__device__ __forceinline__ void mma_tile_tf32(const float* __restrict__ A, size_t lda,
                                              const float* __restrict__ W, size_t ldw,
                                              int kbeg, int nch, float* sA, float* sB,
                                              float cacc[2][NT / 16][4])
{
    constexpr int NFR = NT / 16;
    constexpr int BF4 = NT / 32;
    int tid = threadIdx.x, lane = tid & 31, warp = tid >> 5;
    int wm = (warp & 3) * 32, wn = (warp >> 2) * (NT / 2);
    int qr = lane >> 2, qc = lane & 3;
    float4 ra[4], rb[BF4];
    {
        int kb = kbeg;
#pragma unroll
        for (int j = 0; j < 4; j++) { int idx = j * 256 + tid;
            ra[j] = *(const float4*)(A + (size_t)(idx >> 3) * lda + kb + ((idx & 7) << 2)); }
#pragma unroll
        for (int j = 0; j < BF4; j++) { int idx = j * 256 + tid;
            rb[j] = *(const float4*)(W + (size_t)(idx >> 3) * ldw + kb + ((idx & 7) << 2)); }
    }
    for (int cc = 0; cc < nch; cc++) {
        __syncthreads();
#pragma unroll
        for (int j = 0; j < 4; j++) {
            int idx = j * 256 + tid; int row = idx >> 3; int c0 = (idx & 7) << 2;
            int base = row * PITCH + ((c0 >> 4) << 4) + ((c0 & 15) >> 2);
            sA[base + 0]  = __uint_as_float(f2tf(ra[j].x));
            sA[base + 4]  = __uint_as_float(f2tf(ra[j].y));
            sA[base + 8]  = __uint_as_float(f2tf(ra[j].z));
            sA[base + 12] = __uint_as_float(f2tf(ra[j].w));
        }
#pragma unroll
        for (int j = 0; j < BF4; j++) {
            int idx = j * 256 + tid; int row = idx >> 3; int c0 = (idx & 7) << 2;
            int base = row * PITCH + ((c0 >> 4) << 4) + ((c0 & 15) >> 2);
            sB[base + 0]  = __uint_as_float(f2tf(rb[j].x));
            sB[base + 4]  = __uint_as_float(f2tf(rb[j].y));
            sB[base + 8]  = __uint_as_float(f2tf(rb[j].z));
            sB[base + 12] = __uint_as_float(f2tf(rb[j].w));
        }
        __syncthreads();
        if (cc + 1 < nch) {
            int kb = kbeg + (cc + 1) * 32;
#pragma unroll
            for (int j = 0; j < 4; j++) { int idx = j * 256 + tid;
                ra[j] = *(const float4*)(A + (size_t)(idx >> 3) * lda + kb + ((idx & 7) << 2)); }
#pragma unroll
            for (int j = 0; j < BF4; j++) { int idx = j * 256 + tid;
                rb[j] = *(const float4*)(W + (size_t)(idx >> 3) * ldw + kb + ((idx & 7) << 2)); }
        }
#pragma unroll
        for (int h = 0; h < 2; h++) {
            unsigned bf[NFR][4];
#pragma unroll
            for (int f = 0; f < NFR; f++) {
                float4 v = *(const float4*)(sB + (wn + f * 8 + qr) * PITCH + h * 16 + qc * 4);
                bf[f][0] = __float_as_uint(v.x); bf[f][1] = __float_as_uint(v.y);
                bf[f][2] = __float_as_uint(v.z); bf[f][3] = __float_as_uint(v.w);
            }
#pragma unroll
            for (int mi = 0; mi < 2; mi++) {
                float4 lo = *(const float4*)(sA + (wm + mi * 16 + qr) * PITCH + h * 16 + qc * 4);
                float4 hi = *(const float4*)(sA + (wm + mi * 16 + 8 + qr) * PITCH + h * 16 + qc * 4);
#pragma unroll
                for (int f = 0; f < NFR; f++) {
                    mma8(cacc[mi][f], __float_as_uint(lo.x), __float_as_uint(hi.x),
                         __float_as_uint(lo.y), __float_as_uint(hi.y), bf[f][0], bf[f][1]);
                    mma8(cacc[mi][f], __float_as_uint(lo.z), __float_as_uint(hi.z),
                         __float_as_uint(lo.w), __float_as_uint(hi.w), bf[f][2], bf[f][3]);
                }
            }
        }
    }
}

__global__ void __launch_bounds__(NTHR) xw0_mma(const float* __restrict__ x,
                                                const float* __restrict__ wih,
                                                const float* __restrict__ bih,
                                                const float* __restrict__ bhh)
{
    __shared__ __align__(16) float sA[128 * PITCH];
    __shared__ __align__(16) float sB[64 * PITCH];
    int nt = blockIdx.x, mt = blockIdx.y;
    float cacc[2][4][4] = {};
    mma_tile_tf32<64>(x + (size_t)mt * Dd, (size_t)Tt * Dd,
                      wih + (size_t)nt * 64 * Dd, Dd, 0, Dd / 32, sA, sB, cacc);
    int tid = threadIdx.x, lane = tid & 31, warp = tid >> 5;
    int wm = (warp & 3) * 32, wn = (warp >> 2) * 32;
    int qr = lane >> 2, qc = lane & 3;
    size_t rowbase = (size_t)mt * 128;
#pragma unroll
    for (int mi = 0; mi < 2; mi++)
#pragma unroll
        for (int f = 0; f < 4; f++) {
            int r0 = wm + mi * 16 + qr;
            int cb = nt * 64 + wn + f * 8 + qc * 2;
            float b0 = __ldg(&bih[cb]) + __ldg(&bhh[cb]);
            float b1 = __ldg(&bih[cb + 1]) + __ldg(&bhh[cb + 1]);
            *(float2*)(g_xw0 + (rowbase + r0) * G4H + cb) =
                make_float2(cacc[mi][f][0] + b0, cacc[mi][f][1] + b1);
            *(float2*)(g_xw0 + (rowbase + r0 + 8) * G4H + cb) =
                make_float2(cacc[mi][f][2] + b0, cacc[mi][f][3] + b1);
        }
}

// ---------------- persistent sequential kernel ----------------
__global__ void __launch_bounds__(NTHR, 1) persist_kernel(
    const float* __restrict__ wih, const float* __restrict__ whh,
    const float* __restrict__ kbase, const float* __restrict__ kspl,
    const float* __restrict__ kscl, const float* __restrict__ fc_w,
    const float* __restrict__ fc_b, float* __restrict__ out)
{
    extern __shared__ __align__(16) char smem_raw[];
    __nv_bfloat16* sWg0 = (__nv_bfloat16*)(smem_raw + SM_WG0);
    __nv_bfloat16* sWg1 = (__nv_bfloat16*)(smem_raw + SM_WG1);
    __nv_bfloat16* sWk  = (__nv_bfloat16*)(smem_raw + SM_WK);
    __nv_bfloat16* sAst = (__nv_bfloat16*)(smem_raw + SM_AST);

    int bid = blockIdx.x, tid = threadIdx.x;
    int lane = tid & 31, warp = tid >> 5;
    int qr = lane >> 2, qc = lane & 3;
    int g_nt = bid >> 1, g_mh = bid & 1;     // gates: n-tile(32w), m-half
    int k_nt = bid >> 3, k_ks = bid & 7;     // KAN: n-tile(32w), k-split(576)

    // ---- one-time weight preload into smem ----
    for (int i = tid; i < 32 * 512; i += NTHR) {
        int r = i >> 9, c = i & 511;
        sWg0[r * WP_G0 + c] = __float2bfloat16(whh[(size_t)(g_nt * 32 + r) * 512 + c]);
    }
    for (int i = tid; i < 32 * 1024; i += NTHR) {
        int r = i >> 10, c = i & 1023;
        float v = (c < 512) ? wih[(size_t)G4H * Dd + (size_t)(g_nt * 32 + r) * 512 + c]
                            : whh[(size_t)G4H * Hh + (size_t)(g_nt * 32 + r) * 512 + (c - 512)];
        sWg1[r * WP_G1 + c] = __float2bfloat16(v);
    }
    for (int i = tid; i < 2 * 32 * 576; i += NTHR) {
        int l = i / (32 * 576); int rem = i % (32 * 576);
        int r = rem / 576, c = rem % 576;
        int row = l * 512 + k_nt * 32 + r;
        int kk = k_ks * 576 + c;
        float v;
        if (kk < 512) v = kbase[(size_t)row * 512 + kk];
        else {
            int j = kk - 512; int ii = j >> 3, gg = j & 7;
            v = kspl[((size_t)row * 512 + ii) * 8 + gg] * kscl[(size_t)row * 512 + ii];
        }
        sWk[l * 32 * WP_K + r * WP_K + c] = __float2bfloat16(v);
    }
    __syncthreads();

    bool is_g = (g_nt >> 4) == 2;
    float kt[12], invd[30];
    if (is_g) {
#pragma unroll
        for (int q = 0; q < 12; q++) kt[q] = g_kt[q];
#pragma unroll
        for (int q = 0; q < 30; q++) invd[q] = g_invd[q];
    }

    unsigned nb = 0;
    for (int t = 0; t < Tt; t++) {
#pragma unroll 1
        for (int l = 0; l < 2; l++) {
            // ---- phase 1: gates mma (tile 64x32, full-K) + fused epilogue ----
            {
                float cacc[1][2][4] = {};
                if (l == 0) mma_phase<1, 64>(g_hcat, 1024, g_mh * 64, 0, 8,  sWg0, WP_G0, sAst, cacc);
                else        mma_phase<1, 64>(g_hcat, 1024, g_mh * 64, 0, 16, sWg1, WP_G1, sAst, cacc);
                int wm = (warp & 3) * 16, wn = (warp >> 2) * 16;
#pragma unroll
                for (int nf = 0; nf < 2; nf++)
#pragma unroll
                    for (int e = 0; e < 4; e++) {
                        int b = g_mh * 64 + wm + qr + (e >> 1) * 8;
                        int n = g_nt * 32 + wn + nf * 8 + qc * 2 + (e & 1);
                        float pre = (l == 0) ? g_xw0[((size_t)t * Bz + b) * G4H + n] : g_bg1[n];
                        float v = cacc[0][nf][e] + pre;
                        if (!is_g) {
                            g_sig[b * G4H + n] = 1.f / (1.f + __expf(-v));
                        } else {
                            int ii = n - 1024;
                            g_feat[(size_t)b * FEAT + ii] = __float2bfloat16(v / (1.f + __expf(-v)));
                            float bas[11];
#pragma unroll
                            for (int q = 0; q < 11; q++)
                                bas[q] = (v >= kt[q] && v < kt[q + 1]) ? 1.f : 0.f;
#pragma unroll
                            for (int k = 1; k <= 3; k++) {
                                int off = (k == 1) ? 0 : ((k == 2) ? 11 : 21);
#pragma unroll
                                for (int q = 0; q + k < 11; q++) {
                                    float lf = (v - kt[q]) * invd[off + q];
                                    float rf = (kt[q + k + 1] - v) * invd[off + q + 1];
                                    bas[q] = lf * bas[q] + rf * bas[q + 1];
                                }
                            }
                            __nv_bfloat162 p0 = __float22bfloat162_rn(make_float2(bas[0], bas[1]));
                            __nv_bfloat162 p1 = __float22bfloat162_rn(make_float2(bas[2], bas[3]));
                            __nv_bfloat162 p2 = __float22bfloat162_rn(make_float2(bas[4], bas[5]));
                            __nv_bfloat162 p3 = __float22bfloat162_rn(make_float2(bas[6], bas[7]));
                            uint4 u;
                            u.x = *(unsigned*)&p0; u.y = *(unsigned*)&p1;
                            u.z = *(unsigned*)&p2; u.w = *(unsigned*)&p3;
                            *(uint4*)&g_feat[(size_t)b * FEAT + Hh + ii * 8] = u;
                        }
                    }
            }
            gsync(++nb * NBLK);

            // ---- phase 2: KAN mma (tile 128x32, k-split x8) ----
            {
                float cacc[2][2][4] = {};
                mma_phase<2, 32>(g_feat, FEAT, 0, k_ks * 576, 18,
                                 sWk + l * 32 * WP_K, WP_K, sAst, cacc);
                int wm = (warp & 3) * 32, wn = (warp >> 2) * 16;
#pragma unroll
                for (int mi = 0; mi < 2; mi++)
#pragma unroll
                    for (int nf = 0; nf < 2; nf++) {
                        int r0 = wm + mi * 16 + qr;
                        int cb = k_nt * 32 + wn + nf * 8 + qc * 2;
                        *(float2*)&g_part[k_ks][r0 * Hh + cb] =
                            make_float2(cacc[mi][nf][0], cacc[mi][nf][1]);
                        *(float2*)&g_part[k_ks][(r0 + 8) * Hh + cb] =
                            make_float2(cacc[mi][nf][2], cacc[mi][nf][3]);
                    }
            }
            gsync(++nb * NBLK);

            // ---- phase 3: reduce partials + LSTM cell update ----
            {
#pragma unroll
                for (int it = 0; it < 2; it++) {
                    int idx = it * 32768 + bid * NTHR + tid;
                    float v = 0.f;
#pragma unroll
                    for (int s = 0; s < 8; s++) v += __ldcg(&g_part[s][idx]);
                    int b = idx >> 9, o = idx & 511;
                    float ig = __ldcg(&g_sig[b * G4H + o]);
                    float fg = __ldcg(&g_sig[b * G4H + 512 + o]);
                    float og = __ldcg(&g_sig[b * G4H + 1536 + o]);
                    float c = fg * g_c[l * Bz * Hh + idx] + ig * v;
                    g_c[l * Bz * Hh + idx] = c;
                    g_hcat[b * 1024 + l * 512 + o] = __float2bfloat16(og * tanhf(c));
                }
            }
            gsync(++nb * NBLK);
        }
    }

    // ---- final FC: out = h1 @ fc_w^T + fc_b ----
    {
        int idx = bid * NTHR + tid;       // 0..32767 == Bz*Oo
        int o = idx >> 7, b = idx & 127;
        float s = fc_b[o];
        const __nv_bfloat16* hp = &g_hcat[b * 1024 + 512];
        const float* wp = &fc_w[(size_t)o * Hh];
#pragma unroll 8
        for (int k = 0; k < Hh; k++) s += __bfloat162float(__ldcg(&hp[k])) * wp[k];
        out[b * Oo + o] = s;
    }
}

// ---------------- launch ----------------
extern "C" void kernel_launch(void* const* d_in, const int* in_sizes, int n_in,
                              void* d_out, int out_size)
{
    const float* x     = (const float*)d_in[0];
    const float* wih   = (const float*)d_in[1];
    const float* whh   = (const float*)d_in[2];
    const float* bih   = (const float*)d_in[3];
    const float* bhh   = (const float*)d_in[4];
    const float* kbase = (const float*)d_in[5];
    const float* kspl  = (const float*)d_in[6];
    const float* kscl  = (const float*)d_in[7];
    const float* grid  = (const float*)d_in[8];
    const float* fc_w  = (const float*)d_in[9];
    const float* fc_b  = (const float*)d_in[10];
    float* out = (float*)d_out;

    cudaFuncSetAttribute(persist_kernel, cudaFuncAttributeMaxDynamicSharedMemorySize, SMEM_TOTAL);

    init_kernel<<<512, NTHR>>>(bih, bhh, grid);
    dim3 gg(G4H / 64, (Tt * Bz) / 128);
    xw0_mma<<<gg, NTHR>>>(x, wih, bih, bhh);
    persist_kernel<<<NBLK, NTHR, SMEM_TOTAL>>>(wih, whh, kbase, kspl, kscl, fc_w, fc_b, out);
}

// round 4
// speedup vs baseline: 5.8772x; 1.1750x over previous
#include <cuda_runtime.h>
#include <cuda_bf16.h>
#include <math.h>

// Problem constants
#define Bz    128
#define Tt    1024
#define Dd    512
#define Hh    512
#define Oo    256
#define G4H   2048
#define FEAT  4608
#define NBLK  128
#define NTHR  256
#define PITCH 48        // tf32 xw0 path smem pitch (floats)

// persist kernel smem layout (bytes) — exact 227KB fit
#define WP_G0 520
#define WP_G1 1032
#define WP_K  296
#define SM_WG0 0
#define SM_WG1 33280
#define SM_WK  99328
#define SM_AST 175104
#define SM_STRIDE 14336
#define SMEM_TOTAL 232448

// ---------------- device scratch ----------------
__device__ float g_xw0[(size_t)Tt * Bz * G4H];   // x@wih0^T + bih0 + bhh0 (fp32)
__device__ float g_bg1[G4H];
__device__ __nv_bfloat16 g_hcat[Bz * 1024];      // [h0 | h1] bf16
__device__ float g_sig[Bz * G4H];
__device__ __nv_bfloat16 g_feat[(size_t)Bz * FEAT];
__device__ float g_part[16][Bz * Hh];
__device__ float g_kt[12];
__device__ float g_invd[30];
__device__ unsigned g_bar;

// ---------------- grid barrier: release/acquire, no L1 flush ----------------
__device__ __forceinline__ void gsync(unsigned target) {
    __syncthreads();
    if (threadIdx.x == 0) {
        asm volatile("red.release.gpu.global.add.u32 [%0], 1;" :: "l"(&g_bar) : "memory");
        unsigned v;
        do {
            asm volatile("ld.acquire.gpu.global.u32 %0, [%1];" : "=r"(v) : "l"(&g_bar) : "memory");
        } while (v < target);
    }
    __syncthreads();
}

// ---------------- bf16 mma primitives ----------------
__device__ __forceinline__ void ldm_x4(unsigned &r0, unsigned &r1, unsigned &r2, unsigned &r3, unsigned addr) {
    asm volatile("ldmatrix.sync.aligned.m8n8.x4.shared.b16 {%0,%1,%2,%3}, [%4];"
                 : "=r"(r0), "=r"(r1), "=r"(r2), "=r"(r3) : "r"(addr));
}
__device__ __forceinline__ void mma16816(float c[4], unsigned a0, unsigned a1, unsigned a2, unsigned a3,
                                         unsigned b0, unsigned b1) {
    asm volatile("mma.sync.aligned.m16n8k16.row.col.f32.bf16.bf16.f32 "
                 "{%0,%1,%2,%3},{%4,%5,%6,%7},{%8,%9},{%0,%1,%2,%3};"
                 : "+f"(c[0]), "+f"(c[1]), "+f"(c[2]), "+f"(c[3])
                 : "r"(a0), "r"(a1), "r"(a2), "r"(a3), "r"(b0), "r"(b1));
}

// ---------------- mma phase ----------------
// C((MI*64) x (NW*32)) += A @ W^T. Weights resident in smem; A streamed, 4-stage cp.async.
// 8 warps: 4m x 2n. Warp tile (MI*16) x (NW*16).
template<int MI, int NW, int KCH>
__device__ __forceinline__ void mma_phase(
    const __nv_bfloat16* __restrict__ Ag, int lda, int arow0, int kbeg, int nch,
    const __nv_bfloat16* sW, int wp, __nv_bfloat16* sA, float cacc[MI][NW * 2][4])
{
    constexpr int AP  = KCH + 8;
    constexpr int OPR = KCH / 8;                       // 16B ops per A row
    constexpr int NOPS = (MI * 64) * KCH / 8 / NTHR;   // ops per thread per chunk
    int tid = threadIdx.x, lane = tid & 31, warp = tid >> 5;
    int wm = (warp & 3) * (MI * 16), wn = (warp >> 2) * (NW * 16);
    unsigned sWa = (unsigned)__cvta_generic_to_shared(sW);
    unsigned sAa = (unsigned)__cvta_generic_to_shared(sA);

    auto issue = [&](int cc) {
        const __nv_bfloat16* gb = Ag + (size_t)arow0 * lda + kbeg + cc * KCH;
        unsigned sb = sAa + (cc & 3) * SM_STRIDE;
#pragma unroll
        for (int o = 0; o < NOPS; o++) {
            int idx = o * NTHR + tid;
            int r = idx / OPR, c = (idx % OPR) * 8;
            unsigned sa = sb + (unsigned)(r * AP + c) * 2u;
            const void* ga = gb + (size_t)r * lda + c;
            asm volatile("cp.async.cg.shared.global [%0], [%1], 16;" :: "r"(sa), "l"(ga) : "memory");
        }
        asm volatile("cp.async.commit_group;" ::: "memory");
    };

    for (int s = 0; s < 3; s++) {
        if (s < nch) issue(s);
        else asm volatile("cp.async.commit_group;" ::: "memory");
    }

    int a_r = (lane & 7) + ((lane >> 3) & 1) * 8;
    int a_k = ((lane >> 4) & 1) * 8;
    int b_r = (lane & 7) + ((lane >> 4) & 1) * 8;
    int b_k = ((lane >> 3) & 1) * 8;
    unsigned bbase[NW];
#pragma unroll
    for (int nw = 0; nw < NW; nw++)
        bbase[nw] = sWa + (unsigned)((wn + nw * 16 + b_r) * wp + b_k) * 2u;

    for (int cc = 0; cc < nch; cc++) {
        asm volatile("cp.async.wait_group 2;" ::: "memory");
        __syncthreads();
        if (cc + 3 < nch) issue(cc + 3);
        else asm volatile("cp.async.commit_group;" ::: "memory");

        unsigned sb = sAa + (cc & 3) * SM_STRIDE;
        unsigned ab[MI];
#pragma unroll
        for (int mi = 0; mi < MI; mi++)
            ab[mi] = sb + (unsigned)((wm + mi * 16 + a_r) * AP + a_k) * 2u;
#pragma unroll
        for (int ks = 0; ks < KCH / 16; ks++) {
            unsigned a0[MI], a1[MI], a2[MI], a3[MI];
#pragma unroll
            for (int mi = 0; mi < MI; mi++)
                ldm_x4(a0[mi], a1[mi], a2[mi], a3[mi], ab[mi] + ks * 32);
#pragma unroll
            for (int nw = 0; nw < NW; nw++) {
                unsigned b0, b1, b2, b3;
                ldm_x4(b0, b1, b2, b3, bbase[nw] + (unsigned)(cc * KCH + ks * 16) * 2u);
#pragma unroll
                for (int mi = 0; mi < MI; mi++) {
                    mma16816(cacc[mi][nw * 2 + 0], a0[mi], a1[mi], a2[mi], a3[mi], b0, b1);
                    mma16816(cacc[mi][nw * 2 + 1], a0[mi], a1[mi], a2[mi], a3[mi], b2, b3);
                }
            }
        }
    }
}

// ---------------- tiny init ----------------
__global__ void init_kernel(const float* __restrict__ bih, const float* __restrict__ bhh,
                            const float* __restrict__ grid)
{
    size_t stride = (size_t)gridDim.x * blockDim.x;
    size_t t0 = (size_t)blockIdx.x * blockDim.x + threadIdx.x;
    for (size_t i = t0; i < G4H; i += stride) g_bg1[i] = bih[G4H + i] + bhh[G4H + i];
    for (size_t i = t0; i < (size_t)Bz * 1024; i += stride) g_hcat[i] = __float2bfloat16(0.f);
    for (size_t i = t0; i < 12; i += stride) g_kt[i] = grid[i];
    for (size_t i = t0; i < 30; i += stride) {
        int j = (int)i; int k, jj;
        if (j < 11)      { k = 1; jj = j; }
        else if (j < 21) { k = 2; jj = j - 11; }
        else             { k = 3; jj = j - 21; }
        g_invd[i] = 1.0f / (grid[jj + k] - grid[jj]);
    }
    if (t0 == 0) g_bar = 0u;
}

// ---------------- tf32 xw0 precompute (unchanged, proven) ----------------
__device__ __forceinline__ unsigned f2tf(float x) {
    unsigned u; asm("cvt.rna.tf32.f32 %0, %1;" : "=r"(u) : "f"(x)); return u;
}
__device__ __forceinline__ void mma8(float c[4], unsigned a0, unsigned a1, unsigned a2, unsigned a3,
                                     unsigned b0, unsigned b1) {
    asm volatile("mma.sync.aligned.m16n8k8.row.col.f32.tf32.tf32.f32 "
                 "{%0,%1,%2,%3},{%4,%5,%6,%7},{%8,%9},{%0,%1,%2,%3};"
                 : "+f"(c[0]), "+f"(c[1]), "+f"(c[2]), "+f"(c[3])
                 : "r"(a0), "r"(a1), "r"(a2), "r"(a3), "r"(b0), "r"(b1));
}
template<int NT>
__device__ __forceinline__ void mma_tile_tf32(const float* __restrict__ A, size_t lda,
                                              const float* __restrict__ W, size_t ldw,
                                              int kbeg, int nch, float* sA, float* sB,
                                              float cacc[2][NT / 16][4])
{
    constexpr int NFR = NT / 16;
    constexpr int BF4 = NT / 32;
    int tid = threadIdx.x, lane = tid & 31, warp = tid >> 5;
    int wm = (warp & 3) * 32, wn = (warp >> 2) * (NT / 2);
    int qr = lane >> 2, qc = lane & 3;
    float4 ra[4], rb[BF4];
    {
        int kb = kbeg;
#pragma unroll
        for (int j = 0; j < 4; j++) { int idx = j * 256 + tid;
            ra[j] = *(const float4*)(A + (size_t)(idx >> 3) * lda + kb + ((idx & 7) << 2)); }
#pragma unroll
        for (int j = 0; j < BF4; j++) { int idx = j * 256 + tid;
            rb[j] = *(const float4*)(W + (size_t)(idx >> 3) * ldw + kb + ((idx & 7) << 2)); }
    }
    for (int cc = 0; cc < nch; cc++) {
        __syncthreads();
#pragma unroll
        for (int j = 0; j < 4; j++) {
            int idx = j * 256 + tid; int row = idx >> 3; int c0 = (idx & 7) << 2;
            int base = row * PITCH + ((c0 >> 4) << 4) + ((c0 & 15) >> 2);
            sA[base + 0]  = __uint_as_float(f2tf(ra[j].x));
            sA[base + 4]  = __uint_as_float(f2tf(ra[j].y));
            sA[base + 8]  = __uint_as_float(f2tf(ra[j].z));
            sA[base + 12] = __uint_as_float(f2tf(ra[j].w));
        }
#pragma unroll
        for (int j = 0; j < BF4; j++) {
            int idx = j * 256 + tid; int row = idx >> 3; int c0 = (idx & 7) << 2;
            int base = row * PITCH + ((c0 >> 4) << 4) + ((c0 & 15) >> 2);
            sB[base + 0]  = __uint_as_float(f2tf(rb[j].x));
            sB[base + 4]  = __uint_as_float(f2tf(rb[j].y));
            sB[base + 8]  = __uint_as_float(f2tf(rb[j].z));
            sB[base + 12] = __uint_as_float(f2tf(rb[j].w));
        }
        __syncthreads();
        if (cc + 1 < nch) {
            int kb = kbeg + (cc + 1) * 32;
#pragma unroll
            for (int j = 0; j < 4; j++) { int idx = j * 256 + tid;
                ra[j] = *(const float4*)(A + (size_t)(idx >> 3) * lda + kb + ((idx & 7) << 2)); }
#pragma unroll
            for (int j = 0; j < BF4; j++) { int idx = j * 256 + tid;
                rb[j] = *(const float4*)(W + (size_t)(idx >> 3) * ldw + kb + ((idx & 7) << 2)); }
        }
#pragma unroll
        for (int h = 0; h < 2; h++) {
            unsigned bf[NFR][4];
#pragma unroll
            for (int f = 0; f < NFR; f++) {
                float4 v = *(const float4*)(sB + (wn + f * 8 + qr) * PITCH + h * 16 + qc * 4);
                bf[f][0] = __float_as_uint(v.x); bf[f][1] = __float_as_uint(v.y);
                bf[f][2] = __float_as_uint(v.z); bf[f][3] = __float_as_uint(v.w);
            }
#pragma unroll
            for (int mi = 0; mi < 2; mi++) {
                float4 lo = *(const float4*)(sA + (wm + mi * 16 + qr) * PITCH + h * 16 + qc * 4);
                float4 hi = *(const float4*)(sA + (wm + mi * 16 + 8 + qr) * PITCH + h * 16 + qc * 4);
#pragma unroll
                for (int f = 0; f < NFR; f++) {
                    mma8(cacc[mi][f], __float_as_uint(lo.x), __float_as_uint(hi.x),
                         __float_as_uint(lo.y), __float_as_uint(hi.y), bf[f][0], bf[f][1]);
                    mma8(cacc[mi][f], __float_as_uint(lo.z), __float_as_uint(hi.z),
                         __float_as_uint(lo.w), __float_as_uint(hi.w), bf[f][2], bf[f][3]);
                }
            }
        }
    }
}

__global__ void __launch_bounds__(NTHR) xw0_mma(const float* __restrict__ x,
                                                const float* __restrict__ wih,
                                                const float* __restrict__ bih,
                                                const float* __restrict__ bhh)
{
    __shared__ __align__(16) float sA[128 * PITCH];
    __shared__ __align__(16) float sB[64 * PITCH];
    int nt = blockIdx.x, mt = blockIdx.y;
    float cacc[2][4][4] = {};
    mma_tile_tf32<64>(x + (size_t)mt * Dd, (size_t)Tt * Dd,
                      wih + (size_t)nt * 64 * Dd, Dd, 0, Dd / 32, sA, sB, cacc);
    int tid = threadIdx.x, lane = tid & 31, warp = tid >> 5;
    int wm = (warp & 3) * 32, wn = (warp >> 2) * 32;
    int qr = lane >> 2, qc = lane & 3;
    size_t rowbase = (size_t)mt * 128;
#pragma unroll
    for (int mi = 0; mi < 2; mi++)
#pragma unroll
        for (int f = 0; f < 4; f++) {
            int r0 = wm + mi * 16 + qr;
            int cb = nt * 64 + wn + f * 8 + qc * 2;
            float b0 = __ldg(&bih[cb]) + __ldg(&bhh[cb]);
            float b1 = __ldg(&bih[cb + 1]) + __ldg(&bhh[cb + 1]);
            *(float2*)(g_xw0 + (rowbase + r0) * G4H + cb) =
                make_float2(cacc[mi][f][0] + b0, cacc[mi][f][1] + b1);
            *(float2*)(g_xw0 + (rowbase + r0 + 8) * G4H + cb) =
                make_float2(cacc[mi][f][2] + b0, cacc[mi][f][3] + b1);
        }
}

// ---------------- persistent sequential kernel ----------------
__global__ void __launch_bounds__(NTHR, 1) persist_kernel(
    const float* __restrict__ wih, const float* __restrict__ whh,
    const float* __restrict__ kbase, const float* __restrict__ kspl,
    const float* __restrict__ kscl, const float* __restrict__ fc_w,
    const float* __restrict__ fc_b, float* __restrict__ out)
{
    extern __shared__ __align__(16) char smem_raw[];
    __nv_bfloat16* sWg0 = (__nv_bfloat16*)(smem_raw + SM_WG0);
    __nv_bfloat16* sWg1 = (__nv_bfloat16*)(smem_raw + SM_WG1);
    __nv_bfloat16* sWk  = (__nv_bfloat16*)(smem_raw + SM_WK);
    __nv_bfloat16* sAst = (__nv_bfloat16*)(smem_raw + SM_AST);

    int bid = blockIdx.x, tid = threadIdx.x;
    int lane = tid & 31, warp = tid >> 5;
    int qr = lane >> 2, qc = lane & 3;
    int g_nt = bid >> 1, g_mh = bid & 1;     // gates: 64 n-tiles(32w) x 2 m-halves
    int k_nt = bid >> 4, k_ks = bid & 15;    // KAN:   8 n-tiles(64w) x 16 k-splits(288)

    // ---- one-time weight preload into smem ----
    for (int i = tid; i < 32 * 512; i += NTHR) {
        int r = i >> 9, c = i & 511;
        sWg0[r * WP_G0 + c] = __float2bfloat16(whh[(size_t)(g_nt * 32 + r) * 512 + c]);
    }
    for (int i = tid; i < 32 * 1024; i += NTHR) {
        int r = i >> 10, c = i & 1023;
        float v = (c < 512) ? wih[(size_t)G4H * Dd + (size_t)(g_nt * 32 + r) * 512 + c]
                            : whh[(size_t)G4H * Hh + (size_t)(g_nt * 32 + r) * 512 + (c - 512)];
        sWg1[r * WP_G1 + c] = __float2bfloat16(v);
    }
    for (int i = tid; i < 2 * 64 * 288; i += NTHR) {
        int l = i / (64 * 288); int rem = i % (64 * 288);
        int r = rem / 288, c = rem % 288;
        int row = l * 512 + k_nt * 64 + r;
        int kk = k_ks * 288 + c;
        float v;
        if (kk < 512) v = kbase[(size_t)row * 512 + kk];
        else {
            int j = kk - 512; int ii = j >> 3, gg = j & 7;
            v = kspl[((size_t)row * 512 + ii) * 8 + gg] * kscl[(size_t)row * 512 + ii];
        }
        sWk[(l * 64 + r) * WP_K + c] = __float2bfloat16(v);
    }
    __syncthreads();

    bool is_g = (g_nt >> 4) == 2;
    float kt[12], invd[30];
    if (is_g) {
#pragma unroll
        for (int q = 0; q < 12; q++) kt[q] = g_kt[q];
#pragma unroll
        for (int q = 0; q < 30; q++) invd[q] = g_invd[q];
    }

    // epilogue element coordinates for gates phase
    int wmg = (warp & 3) * 16, wng = (warp >> 2) * 16;
    int eb0 = g_mh * 64 + wmg + qr;                 // row (b), +8 for second
    int en0 = g_nt * 32 + wng + qc * 2;             // col (n), +nf*8, +1

    // g_bg1 preload (l=1 'pre', constant over t)
    float2 pb[2][2];
#pragma unroll
    for (int nf = 0; nf < 2; nf++)
#pragma unroll
        for (int r = 0; r < 2; r++)
            pb[nf][r] = *(const float2*)&g_bg1[en0 + nf * 8];   // same for both rows

    // cell state in registers (block-static phase-3 mapping)
    int p3idx = (bid * NTHR + tid) * 2;             // covers 2 consecutive elements
    float2 creg[2] = {make_float2(0.f, 0.f), make_float2(0.f, 0.f)};

    unsigned nb = 0;
    for (int t = 0; t < Tt; t++) {
#pragma unroll 1
        for (int l = 0; l < 2; l++) {
            // ---- phase 1: gates mma + fused epilogue ----
            {
                // prefetch xw0 'pre' operands (DRAM latency hides behind mma)
                float2 pre[2][2];
                if (l == 0) {
#pragma unroll
                    for (int nf = 0; nf < 2; nf++)
#pragma unroll
                        for (int r = 0; r < 2; r++)
                            pre[nf][r] = __ldcs((const float2*)&g_xw0[
                                ((size_t)t * Bz + eb0 + r * 8) * G4H + en0 + nf * 8]);
                } else {
#pragma unroll
                    for (int nf = 0; nf < 2; nf++)
#pragma unroll
                        for (int r = 0; r < 2; r++) pre[nf][r] = pb[nf][r];
                }

                float cacc[1][2][4] = {};
                if (l == 0) mma_phase<1, 1, 64>(g_hcat, 1024, g_mh * 64, 0, 8,  sWg0, WP_G0, sAst, cacc);
                else        mma_phase<1, 1, 64>(g_hcat, 1024, g_mh * 64, 0, 16, sWg1, WP_G1, sAst, cacc);

#pragma unroll
                for (int nf = 0; nf < 2; nf++)
#pragma unroll
                    for (int r = 0; r < 2; r++) {
                        int b = eb0 + r * 8;
                        int n = en0 + nf * 8;
                        float v0 = cacc[0][nf][r * 2 + 0] + pre[nf][r].x;
                        float v1 = cacc[0][nf][r * 2 + 1] + pre[nf][r].y;
                        if (!is_g) {
                            *(float2*)&g_sig[b * G4H + n] = make_float2(
                                1.f / (1.f + __expf(-v0)), 1.f / (1.f + __expf(-v1)));
                        } else {
#pragma unroll
                            for (int e = 0; e < 2; e++) {
                                float v = e ? v1 : v0;
                                int ii = n + e - 1024;
                                g_feat[(size_t)b * FEAT + ii] =
                                    __float2bfloat16(v / (1.f + __expf(-v)));
                                float bas[11];
#pragma unroll
                                for (int q = 0; q < 11; q++)
                                    bas[q] = (v >= kt[q] && v < kt[q + 1]) ? 1.f : 0.f;
#pragma unroll
                                for (int k = 1; k <= 3; k++) {
                                    int off = (k == 1) ? 0 : ((k == 2) ? 11 : 21);
#pragma unroll
                                    for (int q = 0; q + k < 11; q++) {
                                        float lf = (v - kt[q]) * invd[off + q];
                                        float rf = (kt[q + k + 1] - v) * invd[off + q + 1];
                                        bas[q] = lf * bas[q] + rf * bas[q + 1];
                                    }
                                }
                                __nv_bfloat162 p0 = __float22bfloat162_rn(make_float2(bas[0], bas[1]));
                                __nv_bfloat162 p1 = __float22bfloat162_rn(make_float2(bas[2], bas[3]));
                                __nv_bfloat162 p2 = __float22bfloat162_rn(make_float2(bas[4], bas[5]));
                                __nv_bfloat162 p3 = __float22bfloat162_rn(make_float2(bas[6], bas[7]));
                                uint4 u;
                                u.x = *(unsigned*)&p0; u.y = *(unsigned*)&p1;
                                u.z = *(unsigned*)&p2; u.w = *(unsigned*)&p3;
                                *(uint4*)&g_feat[(size_t)b * FEAT + Hh + ii * 8] = u;
                            }
                        }
                    }
            }
            gsync(++nb * NBLK);

            // ---- phase 2: KAN mma (n-tile 64, k-split x16) ----
            {
                float cacc[2][4][4] = {};
                mma_phase<2, 2, 48>(g_feat, FEAT, 0, k_ks * 288, 6,
                                    sWk + (size_t)l * 64 * WP_K, WP_K, sAst, cacc);
                int wm = (warp & 3) * 32, wn = (warp >> 2) * 32;
#pragma unroll
                for (int mi = 0; mi < 2; mi++)
#pragma unroll
                    for (int f = 0; f < 4; f++) {
                        int r0 = wm + mi * 16 + qr;
                        int cb = k_nt * 64 + wn + (f >> 1) * 16 + (f & 1) * 8 + qc * 2;
                        *(float2*)&g_part[k_ks][r0 * Hh + cb] =
                            make_float2(cacc[mi][f][0], cacc[mi][f][1]);
                        *(float2*)&g_part[k_ks][(r0 + 8) * Hh + cb] =
                            make_float2(cacc[mi][f][2], cacc[mi][f][3]);
                    }
            }
            gsync(++nb * NBLK);

            // ---- phase 3: reduce 16 partials + LSTM cell update (c in regs) ----
            {
                int idx = p3idx;
                float2 v = make_float2(0.f, 0.f);
#pragma unroll
                for (int s = 0; s < 16; s++) {
                    float2 p = __ldcg((const float2*)&g_part[s][idx]);
                    v.x += p.x; v.y += p.y;
                }
                int b = idx >> 9, o = idx & 511;
                float2 ig = __ldcg((const float2*)&g_sig[b * G4H + o]);
                float2 fg = __ldcg((const float2*)&g_sig[b * G4H + 512 + o]);
                float2 og = __ldcg((const float2*)&g_sig[b * G4H + 1536 + o]);
                float c0 = fg.x * creg[l].x + ig.x * v.x;
                float c1 = fg.y * creg[l].y + ig.y * v.y;
                creg[l] = make_float2(c0, c1);
                __nv_bfloat162 h2 = __float22bfloat162_rn(
                    make_float2(og.x * tanhf(c0), og.y * tanhf(c1)));
                *(unsigned*)&g_hcat[b * 1024 + l * 512 + o] = *(unsigned*)&h2;
            }
            gsync(++nb * NBLK);
        }
    }

    // ---- final FC: out = h1 @ fc_w^T + fc_b ----
    {
        int idx = bid * NTHR + tid;       // 0..32767 == Bz*Oo
        int o = idx >> 7, b = idx & 127;
        float s = fc_b[o];
        const __nv_bfloat16* hp = &g_hcat[b * 1024 + 512];
        const float* wp = &fc_w[(size_t)o * Hh];
#pragma unroll 8
        for (int k = 0; k < Hh; k++) s += __bfloat162float(__ldcg(&hp[k])) * wp[k];
        out[b * Oo + o] = s;
    }
}

// ---------------- launch ----------------
extern "C" void kernel_launch(void* const* d_in, const int* in_sizes, int n_in,
                              void* d_out, int out_size)
{
    const float* x     = (const float*)d_in[0];
    const float* wih   = (const float*)d_in[1];
    const float* whh   = (const float*)d_in[2];
    const float* bih   = (const float*)d_in[3];
    const float* bhh   = (const float*)d_in[4];
    const float* kbase = (const float*)d_in[5];
    const float* kspl  = (const float*)d_in[6];
    const float* kscl  = (const float*)d_in[7];
    const float* grid  = (const float*)d_in[8];
    const float* fc_w  = (const float*)d_in[9];
    const float* fc_b  = (const float*)d_in[10];
    float* out = (float*)d_out;

    cudaFuncSetAttribute(persist_kernel, cudaFuncAttributeMaxDynamicSharedMemorySize, SMEM_TOTAL);

    init_kernel<<<512, NTHR>>>(bih, bhh, grid);
    dim3 gg(G4H / 64, (Tt * Bz) / 128);
    xw0_mma<<<gg, NTHR>>>(x, wih, bih, bhh);
    persist_kernel<<<NBLK, NTHR, SMEM_TOTAL>>>(wih, whh, kbase, kspl, kscl, fc_w, fc_b, out);
}

// round 5
// speedup vs baseline: 6.6738x; 1.1355x over previous
#include <cuda_runtime.h>
#include <cuda_bf16.h>
#include <math.h>

// Problem constants
#define Bz    128
#define Tt    1024
#define Dd    512
#define Hh    512
#define Oo    256
#define G4H   2048
#define FEAT  4608
#define NBLK  128
#define NTHR  256
#define PITCH 48        // tf32 xw0 path smem pitch (floats)

// persist kernel smem layout (bytes)
#define WP_G0 520
#define WP_G1 1032
#define WP_K  296
#define SM_WG0 0
#define SM_WG1 33280
#define SM_WK  99328
#define SM_AST 175104
#define SM_STRIDE 14336
#define SMEM_TOTAL 232448

// ---------------- device scratch ----------------
__device__ float g_xw0[(size_t)Tt * Bz * G4H];   // x@wih0^T + bih0 + bhh0 (fp32)
__device__ float g_bg1[G4H];
__device__ __nv_bfloat16 g_hcat[Bz * 1024];      // [h0 | h1] bf16
__device__ float g_sig[Bz * G4H];
__device__ __nv_bfloat16 g_feat[(size_t)Bz * FEAT];
__device__ float g_part[16][Bz * Hh];
__device__ float g_kt[12];
__device__ float g_invd[30];
__device__ unsigned g_bar;
__device__ unsigned g_gcnt[8];                   // per-KAN-group sync counters

// ---------------- grid barrier: release/acquire, no L1 flush ----------------
__device__ __forceinline__ void gsync(unsigned target) {
    __syncthreads();
    if (threadIdx.x == 0) {
        asm volatile("red.release.gpu.global.add.u32 [%0], 1;" :: "l"(&g_bar) : "memory");
        unsigned v;
        do {
            asm volatile("ld.acquire.gpu.global.u32 %0, [%1];" : "=r"(v) : "l"(&g_bar) : "memory");
        } while (v < target);
    }
    __syncthreads();
}

// ---------------- bf16 mma primitives ----------------
__device__ __forceinline__ void ldm_x4(unsigned &r0, unsigned &r1, unsigned &r2, unsigned &r3, unsigned addr) {
    asm volatile("ldmatrix.sync.aligned.m8n8.x4.shared.b16 {%0,%1,%2,%3}, [%4];"
                 : "=r"(r0), "=r"(r1), "=r"(r2), "=r"(r3) : "r"(addr));
}
__device__ __forceinline__ void mma16816(float c[4], unsigned a0, unsigned a1, unsigned a2, unsigned a3,
                                         unsigned b0, unsigned b1) {
    asm volatile("mma.sync.aligned.m16n8k16.row.col.f32.bf16.bf16.f32 "
                 "{%0,%1,%2,%3},{%4,%5,%6,%7},{%8,%9},{%0,%1,%2,%3};"
                 : "+f"(c[0]), "+f"(c[1]), "+f"(c[2]), "+f"(c[3])
                 : "r"(a0), "r"(a1), "r"(a2), "r"(a3), "r"(b0), "r"(b1));
}

// ---------------- mma phase (unchanged from R4) ----------------
template<int MI, int NW, int KCH>
__device__ __forceinline__ void mma_phase(
    const __nv_bfloat16* __restrict__ Ag, int lda, int arow0, int kbeg, int nch,
    const __nv_bfloat16* sW, int wp, __nv_bfloat16* sA, float cacc[MI][NW * 2][4])
{
    constexpr int AP  = KCH + 8;
    constexpr int OPR = KCH / 8;
    constexpr int NOPS = (MI * 64) * KCH / 8 / NTHR;
    int tid = threadIdx.x, lane = tid & 31, warp = tid >> 5;
    int wm = (warp & 3) * (MI * 16), wn = (warp >> 2) * (NW * 16);
    unsigned sWa = (unsigned)__cvta_generic_to_shared(sW);
    unsigned sAa = (unsigned)__cvta_generic_to_shared(sA);

    auto issue = [&](int cc) {
        const __nv_bfloat16* gb = Ag + (size_t)arow0 * lda + kbeg + cc * KCH;
        unsigned sb = sAa + (cc & 3) * SM_STRIDE;
#pragma unroll
        for (int o = 0; o < NOPS; o++) {
            int idx = o * NTHR + tid;
            int r = idx / OPR, c = (idx % OPR) * 8;
            unsigned sa = sb + (unsigned)(r * AP + c) * 2u;
            const void* ga = gb + (size_t)r * lda + c;
            asm volatile("cp.async.cg.shared.global [%0], [%1], 16;" :: "r"(sa), "l"(ga) : "memory");
        }
        asm volatile("cp.async.commit_group;" ::: "memory");
    };

    for (int s = 0; s < 3; s++) {
        if (s < nch) issue(s);
        else asm volatile("cp.async.commit_group;" ::: "memory");
    }

    int a_r = (lane & 7) + ((lane >> 3) & 1) * 8;
    int a_k = ((lane >> 4) & 1) * 8;
    int b_r = (lane & 7) + ((lane >> 4) & 1) * 8;
    int b_k = ((lane >> 3) & 1) * 8;
    unsigned bbase[NW];
#pragma unroll
    for (int nw = 0; nw < NW; nw++)
        bbase[nw] = sWa + (unsigned)((wn + nw * 16 + b_r) * wp + b_k) * 2u;

    for (int cc = 0; cc < nch; cc++) {
        asm volatile("cp.async.wait_group 2;" ::: "memory");
        __syncthreads();
        if (cc + 3 < nch) issue(cc + 3);
        else asm volatile("cp.async.commit_group;" ::: "memory");

        unsigned sb = sAa + (cc & 3) * SM_STRIDE;
        unsigned ab[MI];
#pragma unroll
        for (int mi = 0; mi < MI; mi++)
            ab[mi] = sb + (unsigned)((wm + mi * 16 + a_r) * AP + a_k) * 2u;
#pragma unroll
        for (int ks = 0; ks < KCH / 16; ks++) {
            unsigned a0[MI], a1[MI], a2[MI], a3[MI];
#pragma unroll
            for (int mi = 0; mi < MI; mi++)
                ldm_x4(a0[mi], a1[mi], a2[mi], a3[mi], ab[mi] + ks * 32);
#pragma unroll
            for (int nw = 0; nw < NW; nw++) {
                unsigned b0, b1, b2, b3;
                ldm_x4(b0, b1, b2, b3, bbase[nw] + (unsigned)(cc * KCH + ks * 16) * 2u);
#pragma unroll
                for (int mi = 0; mi < MI; mi++) {
                    mma16816(cacc[mi][nw * 2 + 0], a0[mi], a1[mi], a2[mi], a3[mi], b0, b1);
                    mma16816(cacc[mi][nw * 2 + 1], a0[mi], a1[mi], a2[mi], a3[mi], b2, b3);
                }
            }
        }
    }
}

// ---------------- tiny init ----------------
__global__ void init_kernel(const float* __restrict__ bih, const float* __restrict__ bhh,
                            const float* __restrict__ grid)
{
    size_t stride = (size_t)gridDim.x * blockDim.x;
    size_t t0 = (size_t)blockIdx.x * blockDim.x + threadIdx.x;
    for (size_t i = t0; i < G4H; i += stride) g_bg1[i] = bih[G4H + i] + bhh[G4H + i];
    for (size_t i = t0; i < (size_t)Bz * 1024; i += stride) g_hcat[i] = __float2bfloat16(0.f);
    for (size_t i = t0; i < 12; i += stride) g_kt[i] = grid[i];
    for (size_t i = t0; i < 30; i += stride) {
        int j = (int)i; int k, jj;
        if (j < 11)      { k = 1; jj = j; }
        else if (j < 21) { k = 2; jj = j - 11; }
        else             { k = 3; jj = j - 21; }
        g_invd[i] = 1.0f / (grid[jj + k] - grid[jj]);
    }
    if (t0 < 8) g_gcnt[t0] = 0u;
    if (t0 == 0) g_bar = 0u;
}

// ---------------- tf32 xw0 precompute (unchanged, proven) ----------------
__device__ __forceinline__ unsigned f2tf(float x) {
    unsigned u; asm("cvt.rna.tf32.f32 %0, %1;" : "=r"(u) : "f"(x)); return u;
}
__device__ __forceinline__ void mma8(float c[4], unsigned a0, unsigned a1, unsigned a2, unsigned a3,
                                     unsigned b0, unsigned b1) {
    asm volatile("mma.sync.aligned.m16n8k8.row.col.f32.tf32.tf32.f32 "
                 "{%0,%1,%2,%3},{%4,%5,%6,%7},{%8,%9},{%0,%1,%2,%3};"
                 : "+f"(c[0]), "+f"(c[1]), "+f"(c[2]), "+f"(c[3])
                 : "r"(a0), "r"(a1), "r"(a2), "r"(a3), "r"(b0), "r"(b1));
}
template<int NT>
__device__ __forceinline__ void mma_tile_tf32(const float* __restrict__ A, size_t lda,
                                              const float* __restrict__ W, size_t ldw,
                                              int kbeg, int nch, float* sA, float* sB,
                                              float cacc[2][NT / 16][4])
{
    constexpr int NFR = NT / 16;
    constexpr int BF4 = NT / 32;
    int tid = threadIdx.x, lane = tid & 31, warp = tid >> 5;
    int wm = (warp & 3) * 32, wn = (warp >> 2) * (NT / 2);
    int qr = lane >> 2, qc = lane & 3;
    float4 ra[4], rb[BF4];
    {
        int kb = kbeg;
#pragma unroll
        for (int j = 0; j < 4; j++) { int idx = j * 256 + tid;
            ra[j] = *(const float4*)(A + (size_t)(idx >> 3) * lda + kb + ((idx & 7) << 2)); }
#pragma unroll
        for (int j = 0; j < BF4; j++) { int idx = j * 256 + tid;
            rb[j] = *(const float4*)(W + (size_t)(idx >> 3) * ldw + kb + ((idx & 7) << 2)); }
    }
    for (int cc = 0; cc < nch; cc++) {
        __syncthreads();
#pragma unroll
        for (int j = 0; j < 4; j++) {
            int idx = j * 256 + tid; int row = idx >> 3; int c0 = (idx & 7) << 2;
            int base = row * PITCH + ((c0 >> 4) << 4) + ((c0 & 15) >> 2);
            sA[base + 0]  = __uint_as_float(f2tf(ra[j].x));
            sA[base + 4]  = __uint_as_float(f2tf(ra[j].y));
            sA[base + 8]  = __uint_as_float(f2tf(ra[j].z));
            sA[base + 12] = __uint_as_float(f2tf(ra[j].w));
        }
#pragma unroll
        for (int j = 0; j < BF4; j++) {
            int idx = j * 256 + tid; int row = idx >> 3; int c0 = (idx & 7) << 2;
            int base = row * PITCH + ((c0 >> 4) << 4) + ((c0 & 15) >> 2);
            sB[base + 0]  = __uint_as_float(f2tf(rb[j].x));
            sB[base + 4]  = __uint_as_float(f2tf(rb[j].y));
            sB[base + 8]  = __uint_as_float(f2tf(rb[j].z));
            sB[base + 12] = __uint_as_float(f2tf(rb[j].w));
        }
        __syncthreads();
        if (cc + 1 < nch) {
            int kb = kbeg + (cc + 1) * 32;
#pragma unroll
            for (int j = 0; j < 4; j++) { int idx = j * 256 + tid;
                ra[j] = *(const float4*)(A + (size_t)(idx >> 3) * lda + kb + ((idx & 7) << 2)); }
#pragma unroll
            for (int j = 0; j < BF4; j++) { int idx = j * 256 + tid;
                rb[j] = *(const float4*)(W + (size_t)(idx >> 3) * ldw + kb + ((idx & 7) << 2)); }
        }
#pragma unroll
        for (int h = 0; h < 2; h++) {
            unsigned bf[NFR][4];
#pragma unroll
            for (int f = 0; f < NFR; f++) {
                float4 v = *(const float4*)(sB + (wn + f * 8 + qr) * PITCH + h * 16 + qc * 4);
                bf[f][0] = __float_as_uint(v.x); bf[f][1] = __float_as_uint(v.y);
                bf[f][2] = __float_as_uint(v.z); bf[f][3] = __float_as_uint(v.w);
            }
#pragma unroll
            for (int mi = 0; mi < 2; mi++) {
                float4 lo = *(const float4*)(sA + (wm + mi * 16 + qr) * PITCH + h * 16 + qc * 4);
                float4 hi = *(const float4*)(sA + (wm + mi * 16 + 8 + qr) * PITCH + h * 16 + qc * 4);
#pragma unroll
                for (int f = 0; f < NFR; f++) {
                    mma8(cacc[mi][f], __float_as_uint(lo.x), __float_as_uint(hi.x),
                         __float_as_uint(lo.y), __float_as_uint(hi.y), bf[f][0], bf[f][1]);
                    mma8(cacc[mi][f], __float_as_uint(lo.z), __float_as_uint(hi.z),
                         __float_as_uint(lo.w), __float_as_uint(hi.w), bf[f][2], bf[f][3]);
                }
            }
        }
    }
}

__global__ void __launch_bounds__(NTHR) xw0_mma(const float* __restrict__ x,
                                                const float* __restrict__ wih,
                                                const float* __restrict__ bih,
                                                const float* __restrict__ bhh)
{
    __shared__ __align__(16) float sA[128 * PITCH];
    __shared__ __align__(16) float sB[64 * PITCH];
    int nt = blockIdx.x, mt = blockIdx.y;
    float cacc[2][4][4] = {};
    mma_tile_tf32<64>(x + (size_t)mt * Dd, (size_t)Tt * Dd,
                      wih + (size_t)nt * 64 * Dd, Dd, 0, Dd / 32, sA, sB, cacc);
    int tid = threadIdx.x, lane = tid & 31, warp = tid >> 5;
    int wm = (warp & 3) * 32, wn = (warp >> 2) * 32;
    int qr = lane >> 2, qc = lane & 3;
    size_t rowbase = (size_t)mt * 128;
#pragma unroll
    for (int mi = 0; mi < 2; mi++)
#pragma unroll
        for (int f = 0; f < 4; f++) {
            int r0 = wm + mi * 16 + qr;
            int cb = nt * 64 + wn + f * 8 + qc * 2;
            float b0 = __ldg(&bih[cb]) + __ldg(&bhh[cb]);
            float b1 = __ldg(&bih[cb + 1]) + __ldg(&bhh[cb + 1]);
            *(float2*)(g_xw0 + (rowbase + r0) * G4H + cb) =
                make_float2(cacc[mi][f][0] + b0, cacc[mi][f][1] + b1);
            *(float2*)(g_xw0 + (rowbase + r0 + 8) * G4H + cb) =
                make_float2(cacc[mi][f][2] + b0, cacc[mi][f][3] + b1);
        }
}

// ---------------- persistent sequential kernel ----------------
__global__ void __launch_bounds__(NTHR, 1) persist_kernel(
    const float* __restrict__ wih, const float* __restrict__ whh,
    const float* __restrict__ kbase, const float* __restrict__ kspl,
    const float* __restrict__ kscl, const float* __restrict__ fc_w,
    const float* __restrict__ fc_b, float* __restrict__ out)
{
    extern __shared__ __align__(16) char smem_raw[];
    __nv_bfloat16* sWg0 = (__nv_bfloat16*)(smem_raw + SM_WG0);
    __nv_bfloat16* sWg1 = (__nv_bfloat16*)(smem_raw + SM_WG1);
    __nv_bfloat16* sWk  = (__nv_bfloat16*)(smem_raw + SM_WK);
    __nv_bfloat16* sAst = (__nv_bfloat16*)(smem_raw + SM_AST);

    int bid = blockIdx.x, tid = threadIdx.x;
    int lane = tid & 31, warp = tid >> 5;
    int qr = lane >> 2, qc = lane & 3;
    int g_nt = bid >> 1, g_mh = bid & 1;     // gates: 64 n-tiles(32w) x 2 m-halves
    int k_nt = bid >> 4, k_ks = bid & 15;    // KAN:   8 n-tiles(64w) x 16 k-splits(288)

    // ---- one-time weight preload (gate rows permuted: 8 each of i/f/g/o per tile) ----
    for (int i = tid; i < 32 * 512; i += NTHR) {
        int r = i >> 9, c = i & 511;
        int ng = (r >> 3) * 512 + g_nt * 8 + (r & 7);   // permuted global gate index
        sWg0[r * WP_G0 + c] = __float2bfloat16(whh[(size_t)ng * 512 + c]);
    }
    for (int i = tid; i < 32 * 1024; i += NTHR) {
        int r = i >> 10, c = i & 1023;
        int ng = (r >> 3) * 512 + g_nt * 8 + (r & 7);
        float v = (c < 512) ? wih[(size_t)G4H * Dd + (size_t)ng * 512 + c]
                            : whh[(size_t)G4H * Hh + (size_t)ng * 512 + (c - 512)];
        sWg1[r * WP_G1 + c] = __float2bfloat16(v);
    }
    for (int i = tid; i < 2 * 64 * 288; i += NTHR) {
        int l = i / (64 * 288); int rem = i % (64 * 288);
        int r = rem / 288, c = rem % 288;
        int row = l * 512 + k_nt * 64 + r;
        int kk = k_ks * 288 + c;
        float v;
        if (kk < 512) v = kbase[(size_t)row * 512 + kk];
        else {
            int j = kk - 512; int ii = j >> 3, gg = j & 7;
            v = kspl[((size_t)row * 512 + ii) * 8 + gg] * kscl[(size_t)row * 512 + ii];
        }
        sWk[(l * 64 + r) * WP_K + c] = __float2bfloat16(v);
    }
    __syncthreads();

    float kt[12], invd[30];
#pragma unroll
    for (int q = 0; q < 12; q++) kt[q] = g_kt[q];
#pragma unroll
    for (int q = 0; q < 30; q++) invd[q] = g_invd[q];

    // epilogue coordinates (class-permuted columns)
    int wmg = (warp & 3) * 16, wng = (warp >> 2) * 16;
    int eb0 = g_mh * 64 + wmg + qr;                 // row (b), +8 for second
    int encls[2]; bool isg[2];
#pragma unroll
    for (int nf = 0; nf < 2; nf++) {
        int cls = (wng + nf * 8) >> 3;              // warps 0-3: i,f; warps 4-7: g,o
        encls[nf] = cls * 512 + g_nt * 8 + qc * 2;
        isg[nf] = (cls == 2);
    }

    // g_bg1 preload (l=1 'pre', constant over t)
    float2 pb[2];
#pragma unroll
    for (int nf = 0; nf < 2; nf++) pb[nf] = *(const float2*)&g_bg1[encls[nf]];

    // fused-update shard (static): rows k_ks*8..+8, cols k_nt*64..+64
    int upd_b = k_ks * 8 + (tid >> 5);
    int upd_o = k_nt * 64 + (lane << 1);
    float2 creg[2] = {make_float2(0.f, 0.f), make_float2(0.f, 0.f)};

    unsigned nb = 0, gs = 0;
    for (int t = 0; t < Tt; t++) {
#pragma unroll 1
        for (int l = 0; l < 2; l++) {
            // ---- phase 1: gates mma + fused balanced epilogue ----
            {
                float2 pre[2][2];
                if (l == 0) {
#pragma unroll
                    for (int nf = 0; nf < 2; nf++)
#pragma unroll
                        for (int r = 0; r < 2; r++)
                            pre[nf][r] = __ldcs((const float2*)&g_xw0[
                                ((size_t)t * Bz + eb0 + r * 8) * G4H + encls[nf]]);
                } else {
#pragma unroll
                    for (int nf = 0; nf < 2; nf++)
#pragma unroll
                        for (int r = 0; r < 2; r++) pre[nf][r] = pb[nf];
                }

                float cacc[1][2][4] = {};
                if (l == 0) mma_phase<1, 1, 64>(g_hcat, 1024, g_mh * 64, 0, 8,  sWg0, WP_G0, sAst, cacc);
                else        mma_phase<1, 1, 64>(g_hcat, 1024, g_mh * 64, 0, 16, sWg1, WP_G1, sAst, cacc);

#pragma unroll
                for (int nf = 0; nf < 2; nf++)
#pragma unroll
                    for (int r = 0; r < 2; r++) {
                        int b = eb0 + r * 8;
                        float v0 = cacc[0][nf][r * 2 + 0] + pre[nf][r].x;
                        float v1 = cacc[0][nf][r * 2 + 1] + pre[nf][r].y;
                        if (!isg[nf]) {
                            *(float2*)&g_sig[b * G4H + encls[nf]] = make_float2(
                                1.f / (1.f + __expf(-v0)), 1.f / (1.f + __expf(-v1)));
                        } else {
#pragma unroll
                            for (int e = 0; e < 2; e++) {
                                float v = e ? v1 : v0;
                                int ii = encls[nf] + e - 1024;  // g_nt*8 + qc*2 + e
                                g_feat[(size_t)b * FEAT + ii] =
                                    __float2bfloat16(v / (1.f + __expf(-v)));
                                float bas[11];
#pragma unroll
                                for (int q = 0; q < 11; q++)
                                    bas[q] = (v >= kt[q] && v < kt[q + 1]) ? 1.f : 0.f;
#pragma unroll
                                for (int k = 1; k <= 3; k++) {
                                    int off = (k == 1) ? 0 : ((k == 2) ? 11 : 21);
#pragma unroll
                                    for (int q = 0; q + k < 11; q++) {
                                        float lf = (v - kt[q]) * invd[off + q];
                                        float rf = (kt[q + k + 1] - v) * invd[off + q + 1];
                                        bas[q] = lf * bas[q] + rf * bas[q + 1];
                                    }
                                }
                                __nv_bfloat162 p0 = __float22bfloat162_rn(make_float2(bas[0], bas[1]));
                                __nv_bfloat162 p1 = __float22bfloat162_rn(make_float2(bas[2], bas[3]));
                                __nv_bfloat162 p2 = __float22bfloat162_rn(make_float2(bas[4], bas[5]));
                                __nv_bfloat162 p3 = __float22bfloat162_rn(make_float2(bas[6], bas[7]));
                                uint4 u;
                                u.x = *(unsigned*)&p0; u.y = *(unsigned*)&p1;
                                u.z = *(unsigned*)&p2; u.w = *(unsigned*)&p3;
                                *(uint4*)&g_feat[(size_t)b * FEAT + Hh + ii * 8] = u;
                            }
                        }
                    }
            }
            gsync(++nb * NBLK);

            // ---- phase 2: KAN mma + group-sync + fused LSTM update ----
            {
                float cacc[2][4][4] = {};
                mma_phase<2, 2, 48>(g_feat, FEAT, 0, k_ks * 288, 6,
                                    sWk + (size_t)l * 64 * WP_K, WP_K, sAst, cacc);
                int wm = (warp & 3) * 32, wn = (warp >> 2) * 32;
#pragma unroll
                for (int mi = 0; mi < 2; mi++)
#pragma unroll
                    for (int f = 0; f < 4; f++) {
                        int r0 = wm + mi * 16 + qr;
                        int cb = k_nt * 64 + wn + (f >> 1) * 16 + (f & 1) * 8 + qc * 2;
                        *(float2*)&g_part[k_ks][r0 * Hh + cb] =
                            make_float2(cacc[mi][f][0], cacc[mi][f][1]);
                        *(float2*)&g_part[k_ks][(r0 + 8) * Hh + cb] =
                            make_float2(cacc[mi][f][2], cacc[mi][f][3]);
                    }

                // group-sync: wait for all 16 k-split siblings of this n-tile
                ++gs;
                __syncthreads();
                if (tid == 0) {
                    asm volatile("red.release.gpu.global.add.u32 [%0], 1;"
                                 :: "l"(&g_gcnt[k_nt]) : "memory");
                    unsigned v, tgt = gs * 16;
                    do {
                        asm volatile("ld.acquire.gpu.global.u32 %0, [%1];"
                                     : "=r"(v) : "l"(&g_gcnt[k_nt]) : "memory");
                    } while (v < tgt);
                }
                __syncthreads();

                // fused update: this block's static 512-element shard
                {
                    int b = upd_b, o = upd_o;
                    float2 v = make_float2(0.f, 0.f);
#pragma unroll
                    for (int s = 0; s < 16; s++) {
                        float2 p = __ldcg((const float2*)&g_part[s][b * Hh + o]);
                        v.x += p.x; v.y += p.y;
                    }
                    float2 ig = __ldcg((const float2*)&g_sig[b * G4H + o]);
                    float2 fg = __ldcg((const float2*)&g_sig[b * G4H + 512 + o]);
                    float2 og = __ldcg((const float2*)&g_sig[b * G4H + 1536 + o]);
                    float c0 = fg.x * creg[l].x + ig.x * v.x;
                    float c1 = fg.y * creg[l].y + ig.y * v.y;
                    creg[l] = make_float2(c0, c1);
                    __nv_bfloat162 h2 = __float22bfloat162_rn(
                        make_float2(og.x * tanhf(c0), og.y * tanhf(c1)));
                    *(unsigned*)&g_hcat[b * 1024 + l * 512 + o] = *(unsigned*)&h2;
                }
            }
            gsync(++nb * NBLK);
        }
    }

    // ---- final FC: out = h1 @ fc_w^T + fc_b ----
    {
        int idx = bid * NTHR + tid;       // 0..32767 == Bz*Oo
        int o = idx >> 7, b = idx & 127;
        float s = fc_b[o];
        const __nv_bfloat16* hp = &g_hcat[b * 1024 + 512];
        const float* wp = &fc_w[(size_t)o * Hh];
#pragma unroll 8
        for (int k = 0; k < Hh; k++) s += __bfloat162float(__ldcg(&hp[k])) * wp[k];
        out[b * Oo + o] = s;
    }
}

// ---------------- launch ----------------
extern "C" void kernel_launch(void* const* d_in, const int* in_sizes, int n_in,
                              void* d_out, int out_size)
{
    const float* x     = (const float*)d_in[0];
    const float* wih   = (const float*)d_in[1];
    const float* whh   = (const float*)d_in[2];
    const float* bih   = (const float*)d_in[3];
    const float* bhh   = (const float*)d_in[4];
    const float* kbase = (const float*)d_in[5];
    const float* kspl  = (const float*)d_in[6];
    const float* kscl  = (const float*)d_in[7];
    const float* grid  = (const float*)d_in[8];
    const float* fc_w  = (const float*)d_in[9];
    const float* fc_b  = (const float*)d_in[10];
    float* out = (float*)d_out;

    cudaFuncSetAttribute(persist_kernel, cudaFuncAttributeMaxDynamicSharedMemorySize, SMEM_TOTAL);

    init_kernel<<<512, NTHR>>>(bih, bhh, grid);
    dim3 gg(G4H / 64, (Tt * Bz) / 128);
    xw0_mma<<<gg, NTHR>>>(x, wih, bih, bhh);
    persist_kernel<<<NBLK, NTHR, SMEM_TOTAL>>>(wih, whh, kbase, kspl, kscl, fc_w, fc_b, out);
}

// round 6
// speedup vs baseline: 7.6072x; 1.1399x over previous
#include <cuda_runtime.h>
#include <cuda_bf16.h>
#include <math.h>

// Problem constants
#define Bz    128
#define Tt    1024
#define Dd    512
#define Hh    512
#define Oo    256
#define G4H   2048
#define FEAT  4608
#define NBLK  128
#define NTHR  256
#define PITCH 48        // tf32 xw0 path smem pitch (floats)

// persist kernel smem layout (bytes)
#define WP_G0 520
#define WP_G1 1032
#define WP_K  296
#define SM_WG0 0
#define SM_WG1 33280
#define SM_WK  99328
#define SM_AST 175104
#define SM_STRIDE 14336
#define SMEM_TOTAL 232448

// ---------------- device scratch ----------------
__device__ float g_xw0[(size_t)Tt * Bz * G4H];   // x@wih0^T + bih0 + bhh0 (fp32)
__device__ float g_bg1[G4H];
__device__ __nv_bfloat16 g_hcat[Bz * 1024];      // [h0 | h1] bf16
__device__ float g_sig[2][Bz * G4H];             // per-layer sigmoided i/f/o
__device__ __nv_bfloat16 g_feat[2][(size_t)Bz * FEAT];
__device__ float g_part[2][16][Bz * Hh];
__device__ float g_kt[12];
__device__ float g_invd[30];
__device__ unsigned g_bar;
__device__ unsigned g_gcnt[8];                   // per-KAN-group sync counters

// ---------------- grid barrier: release/acquire, no L1 flush ----------------
__device__ __forceinline__ void gsync(unsigned target) {
    __syncthreads();
    if (threadIdx.x == 0) {
        asm volatile("red.release.gpu.global.add.u32 [%0], 1;" :: "l"(&g_bar) : "memory");
        unsigned v;
        do {
            asm volatile("ld.acquire.gpu.global.u32 %0, [%1];" : "=r"(v) : "l"(&g_bar) : "memory");
        } while (v < target);
    }
    __syncthreads();
}

// ---------------- bf16 mma primitives ----------------
__device__ __forceinline__ void ldm_x4(unsigned &r0, unsigned &r1, unsigned &r2, unsigned &r3, unsigned addr) {
    asm volatile("ldmatrix.sync.aligned.m8n8.x4.shared.b16 {%0,%1,%2,%3}, [%4];"
                 : "=r"(r0), "=r"(r1), "=r"(r2), "=r"(r3) : "r"(addr));
}
__device__ __forceinline__ void mma16816(float c[4], unsigned a0, unsigned a1, unsigned a2, unsigned a3,
                                         unsigned b0, unsigned b1) {
    asm volatile("mma.sync.aligned.m16n8k16.row.col.f32.bf16.bf16.f32 "
                 "{%0,%1,%2,%3},{%4,%5,%6,%7},{%8,%9},{%0,%1,%2,%3};"
                 : "+f"(c[0]), "+f"(c[1]), "+f"(c[2]), "+f"(c[3])
                 : "r"(a0), "r"(a1), "r"(a2), "r"(a3), "r"(b0), "r"(b1));
}

// ---------------- merged gates mma: one A stream (hcat K=1024), two weight sets ----
// acc1 accumulates over all 16 chunks (L1, K=1024); acc0 over chunks 0-7 (L0, K=512).
__device__ __forceinline__ void mma_gates(
    const __nv_bfloat16* __restrict__ Ag, int arow0,
    const __nv_bfloat16* sWg0, const __nv_bfloat16* sWg1,
    __nv_bfloat16* sA, float (&acc0)[2][4], float (&acc1)[2][4])
{
    constexpr int KCH = 64, AP = 72, NCH = 16;
    int tid = threadIdx.x, lane = tid & 31, warp = tid >> 5;
    int wm = (warp & 3) * 16, wn = (warp >> 2) * 16;
    unsigned sW0a = (unsigned)__cvta_generic_to_shared(sWg0);
    unsigned sW1a = (unsigned)__cvta_generic_to_shared(sWg1);
    unsigned sAa  = (unsigned)__cvta_generic_to_shared(sA);

    auto issue = [&](int cc) {
        const __nv_bfloat16* gb = Ag + (size_t)arow0 * 1024 + cc * KCH;
        unsigned sb = sAa + (cc & 3) * SM_STRIDE;
#pragma unroll
        for (int o = 0; o < 2; o++) {
            int idx = o * NTHR + tid;
            int r = idx >> 3, c = (idx & 7) * 8;
            unsigned sa = sb + (unsigned)(r * AP + c) * 2u;
            const void* ga = gb + (size_t)r * 1024 + c;
            asm volatile("cp.async.cg.shared.global [%0], [%1], 16;" :: "r"(sa), "l"(ga) : "memory");
        }
        asm volatile("cp.async.commit_group;" ::: "memory");
    };
    issue(0); issue(1); issue(2);

    int a_r = (lane & 7) + ((lane >> 3) & 1) * 8;
    int a_k = ((lane >> 4) & 1) * 8;
    int b_r = (lane & 7) + ((lane >> 4) & 1) * 8;
    int b_k = ((lane >> 3) & 1) * 8;
    unsigned b0base = sW0a + (unsigned)((wn + b_r) * WP_G0 + b_k) * 2u;
    unsigned b1base = sW1a + (unsigned)((wn + b_r) * WP_G1 + b_k) * 2u;

    for (int cc = 0; cc < NCH; cc++) {
        asm volatile("cp.async.wait_group 2;" ::: "memory");
        __syncthreads();
        if (cc + 3 < NCH) issue(cc + 3);
        else asm volatile("cp.async.commit_group;" ::: "memory");
        unsigned ab = sAa + (cc & 3) * SM_STRIDE + (unsigned)((wm + a_r) * AP + a_k) * 2u;
#pragma unroll
        for (int ks = 0; ks < 4; ks++) {
            unsigned a0r, a1r, a2r, a3r;
            ldm_x4(a0r, a1r, a2r, a3r, ab + ks * 32);
            unsigned b0, b1, b2, b3;
            ldm_x4(b0, b1, b2, b3, b1base + (unsigned)(cc * KCH + ks * 16) * 2u);
            mma16816(acc1[0], a0r, a1r, a2r, a3r, b0, b1);
            mma16816(acc1[1], a0r, a1r, a2r, a3r, b2, b3);
            if (cc < 8) {
                unsigned c0, c1, c2, c3;
                ldm_x4(c0, c1, c2, c3, b0base + (unsigned)(cc * KCH + ks * 16) * 2u);
                mma16816(acc0[0], a0r, a1r, a2r, a3r, c0, c1);
                mma16816(acc0[1], a0r, a1r, a2r, a3r, c2, c3);
            }
        }
    }
}

// ---------------- KAN mma phase (proven R4/R5 core) ----------------
template<int MI, int NW, int KCH>
__device__ __forceinline__ void mma_phase(
    const __nv_bfloat16* __restrict__ Ag, int lda, int arow0, int kbeg, int nch,
    const __nv_bfloat16* sW, int wp, __nv_bfloat16* sA, float cacc[MI][NW * 2][4])
{
    constexpr int AP  = KCH + 8;
    constexpr int OPR = KCH / 8;
    constexpr int NOPS = (MI * 64) * KCH / 8 / NTHR;
    int tid = threadIdx.x, lane = tid & 31, warp = tid >> 5;
    int wm = (warp & 3) * (MI * 16), wn = (warp >> 2) * (NW * 16);
    unsigned sWa = (unsigned)__cvta_generic_to_shared(sW);
    unsigned sAa = (unsigned)__cvta_generic_to_shared(sA);

    auto issue = [&](int cc) {
        const __nv_bfloat16* gb = Ag + (size_t)arow0 * lda + kbeg + cc * KCH;
        unsigned sb = sAa + (cc & 3) * SM_STRIDE;
#pragma unroll
        for (int o = 0; o < NOPS; o++) {
            int idx = o * NTHR + tid;
            int r = idx / OPR, c = (idx % OPR) * 8;
            unsigned sa = sb + (unsigned)(r * AP + c) * 2u;
            const void* ga = gb + (size_t)r * lda + c;
            asm volatile("cp.async.cg.shared.global [%0], [%1], 16;" :: "r"(sa), "l"(ga) : "memory");
        }
        asm volatile("cp.async.commit_group;" ::: "memory");
    };

    for (int s = 0; s < 3; s++) {
        if (s < nch) issue(s);
        else asm volatile("cp.async.commit_group;" ::: "memory");
    }

    int a_r = (lane & 7) + ((lane >> 3) & 1) * 8;
    int a_k = ((lane >> 4) & 1) * 8;
    int b_r = (lane & 7) + ((lane >> 4) & 1) * 8;
    int b_k = ((lane >> 3) & 1) * 8;
    unsigned bbase[NW];
#pragma unroll
    for (int nw = 0; nw < NW; nw++)
        bbase[nw] = sWa + (unsigned)((wn + nw * 16 + b_r) * wp + b_k) * 2u;

    for (int cc = 0; cc < nch; cc++) {
        asm volatile("cp.async.wait_group 2;" ::: "memory");
        __syncthreads();
        if (cc + 3 < nch) issue(cc + 3);
        else asm volatile("cp.async.commit_group;" ::: "memory");

        unsigned sb = sAa + (cc & 3) * SM_STRIDE;
        unsigned ab[MI];
#pragma unroll
        for (int mi = 0; mi < MI; mi++)
            ab[mi] = sb + (unsigned)((wm + mi * 16 + a_r) * AP + a_k) * 2u;
#pragma unroll
        for (int ks = 0; ks < KCH / 16; ks++) {
            unsigned a0[MI], a1[MI], a2[MI], a3[MI];
#pragma unroll
            for (int mi = 0; mi < MI; mi++)
                ldm_x4(a0[mi], a1[mi], a2[mi], a3[mi], ab[mi] + ks * 32);
#pragma unroll
            for (int nw = 0; nw < NW; nw++) {
                unsigned b0, b1, b2, b3;
                ldm_x4(b0, b1, b2, b3, bbase[nw] + (unsigned)(cc * KCH + ks * 16) * 2u);
#pragma unroll
                for (int mi = 0; mi < MI; mi++) {
                    mma16816(cacc[mi][nw * 2 + 0], a0[mi], a1[mi], a2[mi], a3[mi], b0, b1);
                    mma16816(cacc[mi][nw * 2 + 1], a0[mi], a1[mi], a2[mi], a3[mi], b2, b3);
                }
            }
        }
    }
}

// ---------------- tiny init ----------------
__global__ void init_kernel(const float* __restrict__ bih, const float* __restrict__ bhh,
                            const float* __restrict__ grid)
{
    size_t stride = (size_t)gridDim.x * blockDim.x;
    size_t t0 = (size_t)blockIdx.x * blockDim.x + threadIdx.x;
    for (size_t i = t0; i < G4H; i += stride) g_bg1[i] = bih[G4H + i] + bhh[G4H + i];
    for (size_t i = t0; i < (size_t)Bz * 1024; i += stride) g_hcat[i] = __float2bfloat16(0.f);
    for (size_t i = t0; i < 12; i += stride) g_kt[i] = grid[i];
    for (size_t i = t0; i < 30; i += stride) {
        int j = (int)i; int k, jj;
        if (j < 11)      { k = 1; jj = j; }
        else if (j < 21) { k = 2; jj = j - 11; }
        else             { k = 3; jj = j - 21; }
        g_invd[i] = 1.0f / (grid[jj + k] - grid[jj]);
    }
    if (t0 < 8) g_gcnt[t0] = 0u;
    if (t0 == 0) g_bar = 0u;
}

// ---------------- tf32 xw0 precompute (unchanged, proven) ----------------
__device__ __forceinline__ unsigned f2tf(float x) {
    unsigned u; asm("cvt.rna.tf32.f32 %0, %1;" : "=r"(u) : "f"(x)); return u;
}
__device__ __forceinline__ void mma8(float c[4], unsigned a0, unsigned a1, unsigned a2, unsigned a3,
                                     unsigned b0, unsigned b1) {
    asm volatile("mma.sync.aligned.m16n8k8.row.col.f32.tf32.tf32.f32 "
                 "{%0,%1,%2,%3},{%4,%5,%6,%7},{%8,%9},{%0,%1,%2,%3};"
                 : "+f"(c[0]), "+f"(c[1]), "+f"(c[2]), "+f"(c[3])
                 : "r"(a0), "r"(a1), "r"(a2), "r"(a3), "r"(b0), "r"(b1));
}
template<int NT>
__device__ __forceinline__ void mma_tile_tf32(const float* __restrict__ A, size_t lda,
                                              const float* __restrict__ W, size_t ldw,
                                              int kbeg, int nch, float* sA, float* sB,
                                              float cacc[2][NT / 16][4])
{
    constexpr int NFR = NT / 16;
    constexpr int BF4 = NT / 32;
    int tid = threadIdx.x, lane = tid & 31, warp = tid >> 5;
    int wm = (warp & 3) * 32, wn = (warp >> 2) * (NT / 2);
    int qr = lane >> 2, qc = lane & 3;
    float4 ra[4], rb[BF4];
    {
        int kb = kbeg;
#pragma unroll
        for (int j = 0; j < 4; j++) { int idx = j * 256 + tid;
            ra[j] = *(const float4*)(A + (size_t)(idx >> 3) * lda + kb + ((idx & 7) << 2)); }
#pragma unroll
        for (int j = 0; j < BF4; j++) { int idx = j * 256 + tid;
            rb[j] = *(const float4*)(W + (size_t)(idx >> 3) * ldw + kb + ((idx & 7) << 2)); }
    }
    for (int cc = 0; cc < nch; cc++) {
        __syncthreads();
#pragma unroll
        for (int j = 0; j < 4; j++) {
            int idx = j * 256 + tid; int row = idx >> 3; int c0 = (idx & 7) << 2;
            int base = row * PITCH + ((c0 >> 4) << 4) + ((c0 & 15) >> 2);
            sA[base + 0]  = __uint_as_float(f2tf(ra[j].x));
            sA[base + 4]  = __uint_as_float(f2tf(ra[j].y));
            sA[base + 8]  = __uint_as_float(f2tf(ra[j].z));
            sA[base + 12] = __uint_as_float(f2tf(ra[j].w));
        }
#pragma unroll
        for (int j = 0; j < BF4; j++) {
            int idx = j * 256 + tid; int row = idx >> 3; int c0 = (idx & 7) << 2;
            int base = row * PITCH + ((c0 >> 4) << 4) + ((c0 & 15) >> 2);
            sB[base + 0]  = __uint_as_float(f2tf(rb[j].x));
            sB[base + 4]  = __uint_as_float(f2tf(rb[j].y));
            sB[base + 8]  = __uint_as_float(f2tf(rb[j].z));
            sB[base + 12] = __uint_as_float(f2tf(rb[j].w));
        }
        __syncthreads();
        if (cc + 1 < nch) {
            int kb = kbeg + (cc + 1) * 32;
#pragma unroll
            for (int j = 0; j < 4; j++) { int idx = j * 256 + tid;
                ra[j] = *(const float4*)(A + (size_t)(idx >> 3) * lda + kb + ((idx & 7) << 2)); }
#pragma unroll
            for (int j = 0; j < BF4; j++) { int idx = j * 256 + tid;
                rb[j] = *(const float4*)(W + (size_t)(idx >> 3) * ldw + kb + ((idx & 7) << 2)); }
        }
#pragma unroll
        for (int h = 0; h < 2; h++) {
            unsigned bf[NFR][4];
#pragma unroll
            for (int f = 0; f < NFR; f++) {
                float4 v = *(const float4*)(sB + (wn + f * 8 + qr) * PITCH + h * 16 + qc * 4);
                bf[f][0] = __float_as_uint(v.x); bf[f][1] = __float_as_uint(v.y);
                bf[f][2] = __float_as_uint(v.z); bf[f][3] = __float_as_uint(v.w);
            }
#pragma unroll
            for (int mi = 0; mi < 2; mi++) {
                float4 lo = *(const float4*)(sA + (wm + mi * 16 + qr) * PITCH + h * 16 + qc * 4);
                float4 hi = *(const float4*)(sA + (wm + mi * 16 + 8 + qr) * PITCH + h * 16 + qc * 4);
#pragma unroll
                for (int f = 0; f < NFR; f++) {
                    mma8(cacc[mi][f], __float_as_uint(lo.x), __float_as_uint(hi.x),
                         __float_as_uint(lo.y), __float_as_uint(hi.y), bf[f][0], bf[f][1]);
                    mma8(cacc[mi][f], __float_as_uint(lo.z), __float_as_uint(hi.z),
                         __float_as_uint(lo.w), __float_as_uint(hi.w), bf[f][2], bf[f][3]);
                }
            }
        }
    }
}

__global__ void __launch_bounds__(NTHR) xw0_mma(const float* __restrict__ x,
                                                const float* __restrict__ wih,
                                                const float* __restrict__ bih,
                                                const float* __restrict__ bhh)
{
    __shared__ __align__(16) float sA[128 * PITCH];
    __shared__ __align__(16) float sB[64 * PITCH];
    int nt = blockIdx.x, mt = blockIdx.y;
    float cacc[2][4][4] = {};
    mma_tile_tf32<64>(x + (size_t)mt * Dd, (size_t)Tt * Dd,
                      wih + (size_t)nt * 64 * Dd, Dd, 0, Dd / 32, sA, sB, cacc);
    int tid = threadIdx.x, lane = tid & 31, warp = tid >> 5;
    int wm = (warp & 3) * 32, wn = (warp >> 2) * 32;
    int qr = lane >> 2, qc = lane & 3;
    size_t rowbase = (size_t)mt * 128;
#pragma unroll
    for (int mi = 0; mi < 2; mi++)
#pragma unroll
        for (int f = 0; f < 4; f++) {
            int r0 = wm + mi * 16 + qr;
            int cb = nt * 64 + wn + f * 8 + qc * 2;
            float b0 = __ldg(&bih[cb]) + __ldg(&bhh[cb]);
            float b1 = __ldg(&bih[cb + 1]) + __ldg(&bhh[cb + 1]);
            *(float2*)(g_xw0 + (rowbase + r0) * G4H + cb) =
                make_float2(cacc[mi][f][0] + b0, cacc[mi][f][1] + b1);
            *(float2*)(g_xw0 + (rowbase + r0 + 8) * G4H + cb) =
                make_float2(cacc[mi][f][2] + b0, cacc[mi][f][3] + b1);
        }
}

// ---------------- persistent sequential kernel (layer-pipelined) ----------------
__global__ void __launch_bounds__(NTHR, 1) persist_kernel(
    const float* __restrict__ wih, const float* __restrict__ whh,
    const float* __restrict__ kbase, const float* __restrict__ kspl,
    const float* __restrict__ kscl, const float* __restrict__ fc_w,
    const float* __restrict__ fc_b, float* __restrict__ out)
{
    extern __shared__ __align__(16) char smem_raw[];
    __nv_bfloat16* sWg0 = (__nv_bfloat16*)(smem_raw + SM_WG0);
    __nv_bfloat16* sWg1 = (__nv_bfloat16*)(smem_raw + SM_WG1);
    __nv_bfloat16* sWk  = (__nv_bfloat16*)(smem_raw + SM_WK);
    __nv_bfloat16* sAst = (__nv_bfloat16*)(smem_raw + SM_AST);

    int bid = blockIdx.x, tid = threadIdx.x;
    int lane = tid & 31, warp = tid >> 5;
    int qr = lane >> 2, qc = lane & 3;
    int g_nt = bid >> 1, g_mh = bid & 1;     // gates: 64 n-tiles(32w) x 2 m-halves
    int k_nt = bid >> 4, k_ks = bid & 15;    // KAN:   8 n-tiles(64w) x 16 k-splits(288)

    // ---- one-time weight preload (gate rows permuted: 8 each of i/f/g/o per tile) ----
    for (int i = tid; i < 32 * 512; i += NTHR) {
        int r = i >> 9, c = i & 511;
        int ng = (r >> 3) * 512 + g_nt * 8 + (r & 7);
        sWg0[r * WP_G0 + c] = __float2bfloat16(whh[(size_t)ng * 512 + c]);
    }
    for (int i = tid; i < 32 * 1024; i += NTHR) {
        int r = i >> 10, c = i & 1023;
        int ng = (r >> 3) * 512 + g_nt * 8 + (r & 7);
        float v = (c < 512) ? wih[(size_t)G4H * Dd + (size_t)ng * 512 + c]
                            : whh[(size_t)G4H * Hh + (size_t)ng * 512 + (c - 512)];
        sWg1[r * WP_G1 + c] = __float2bfloat16(v);
    }
    for (int i = tid; i < 2 * 64 * 288; i += NTHR) {
        int l = i / (64 * 288); int rem = i % (64 * 288);
        int r = rem / 288, c = rem % 288;
        int row = l * 512 + k_nt * 64 + r;
        int kk = k_ks * 288 + c;
        float v;
        if (kk < 512) v = kbase[(size_t)row * 512 + kk];
        else {
            int j = kk - 512; int ii = j >> 3, gg = j & 7;
            v = kspl[((size_t)row * 512 + ii) * 8 + gg] * kscl[(size_t)row * 512 + ii];
        }
        sWk[(l * 64 + r) * WP_K + c] = __float2bfloat16(v);
    }
    __syncthreads();

    float kt[12], invd[30];
#pragma unroll
    for (int q = 0; q < 12; q++) kt[q] = g_kt[q];
#pragma unroll
    for (int q = 0; q < 30; q++) invd[q] = g_invd[q];

    // gates epilogue coordinates (class-permuted columns)
    int wng = (warp >> 2) * 16;
    int eb0 = g_mh * 64 + (warp & 3) * 16 + qr;
    int encls[2]; bool isg[2];
#pragma unroll
    for (int nf = 0; nf < 2; nf++) {
        int cls = (wng + nf * 8) >> 3;
        encls[nf] = cls * 512 + g_nt * 8 + qc * 2;
        isg[nf] = (cls == 2);
    }
    float2 pb[2];
#pragma unroll
    for (int nf = 0; nf < 2; nf++) pb[nf] = *(const float2*)&g_bg1[encls[nf]];

    // fused-update shard (static)
    int upd_b = k_ks * 8 + (tid >> 5);
    int upd_o = k_nt * 64 + (lane << 1);
    float2 creg[2] = {make_float2(0.f, 0.f), make_float2(0.f, 0.f)};

    // ---- helpers ----
    auto gate_epilogue = [&](int l, const float2 (&pre)[2][2], const float (&cc4)[2][4]) {
#pragma unroll
        for (int nf = 0; nf < 2; nf++)
#pragma unroll
            for (int r = 0; r < 2; r++) {
                int b = eb0 + r * 8;
                float v0 = cc4[nf][r * 2 + 0] + pre[nf][r].x;
                float v1 = cc4[nf][r * 2 + 1] + pre[nf][r].y;
                if (!isg[nf]) {
                    *(float2*)&g_sig[l][b * G4H + encls[nf]] = make_float2(
                        1.f / (1.f + __expf(-v0)), 1.f / (1.f + __expf(-v1)));
                } else {
#pragma unroll
                    for (int e = 0; e < 2; e++) {
                        float v = e ? v1 : v0;
                        int ii = encls[nf] + e - 1024;
                        g_feat[l][(size_t)b * FEAT + ii] =
                            __float2bfloat16(v / (1.f + __expf(-v)));
                        float bas[11];
#pragma unroll
                        for (int q = 0; q < 11; q++)
                            bas[q] = (v >= kt[q] && v < kt[q + 1]) ? 1.f : 0.f;
#pragma unroll
                        for (int k = 1; k <= 3; k++) {
                            int off = (k == 1) ? 0 : ((k == 2) ? 11 : 21);
#pragma unroll
                            for (int q = 0; q + k < 11; q++) {
                                float lf = (v - kt[q]) * invd[off + q];
                                float rf = (kt[q + k + 1] - v) * invd[off + q + 1];
                                bas[q] = lf * bas[q] + rf * bas[q + 1];
                            }
                        }
                        __nv_bfloat162 p0 = __float22bfloat162_rn(make_float2(bas[0], bas[1]));
                        __nv_bfloat162 p1 = __float22bfloat162_rn(make_float2(bas[2], bas[3]));
                        __nv_bfloat162 p2 = __float22bfloat162_rn(make_float2(bas[4], bas[5]));
                        __nv_bfloat162 p3 = __float22bfloat162_rn(make_float2(bas[6], bas[7]));
                        uint4 u;
                        u.x = *(unsigned*)&p0; u.y = *(unsigned*)&p1;
                        u.z = *(unsigned*)&p2; u.w = *(unsigned*)&p3;
                        *(uint4*)&g_feat[l][(size_t)b * FEAT + Hh + ii * 8] = u;
                    }
                }
            }
    };

    auto kan_mma_store = [&](int l) {
        float cacc[2][4][4] = {};
        mma_phase<2, 2, 48>(g_feat[l], FEAT, 0, k_ks * 288, 6,
                            sWk + (size_t)l * 64 * WP_K, WP_K, sAst, cacc);
        int wm = (warp & 3) * 32, wn = (warp >> 2) * 32;
#pragma unroll
        for (int mi = 0; mi < 2; mi++)
#pragma unroll
            for (int f = 0; f < 4; f++) {
                int r0 = wm + mi * 16 + qr;
                int cb = k_nt * 64 + wn + (f >> 1) * 16 + (f & 1) * 8 + qc * 2;
                *(float2*)&g_part[l][k_ks][r0 * Hh + cb] =
                    make_float2(cacc[mi][f][0], cacc[mi][f][1]);
                *(float2*)&g_part[l][k_ks][(r0 + 8) * Hh + cb] =
                    make_float2(cacc[mi][f][2], cacc[mi][f][3]);
            }
    };

    unsigned gs = 0;
    auto group_sync = [&]() {
        ++gs;
        __syncthreads();
        if (tid == 0) {
            asm volatile("red.release.gpu.global.add.u32 [%0], 1;"
                         :: "l"(&g_gcnt[k_nt]) : "memory");
            unsigned v, tgt = gs * 16;
            do {
                asm volatile("ld.acquire.gpu.global.u32 %0, [%1];"
                             : "=r"(v) : "l"(&g_gcnt[k_nt]) : "memory");
            } while (v < tgt);
        }
        __syncthreads();
    };

    auto kan_update = [&](int l) {
        int b = upd_b, o = upd_o;
        float2 v = make_float2(0.f, 0.f);
#pragma unroll
        for (int s = 0; s < 16; s++) {
            float2 p = __ldcg((const float2*)&g_part[l][s][b * Hh + o]);
            v.x += p.x; v.y += p.y;
        }
        float2 ig = __ldcg((const float2*)&g_sig[l][b * G4H + o]);
        float2 fg = __ldcg((const float2*)&g_sig[l][b * G4H + 512 + o]);
        float2 og = __ldcg((const float2*)&g_sig[l][b * G4H + 1536 + o]);
        float c0 = fg.x * creg[l].x + ig.x * v.x;
        float c1 = fg.y * creg[l].y + ig.y * v.y;
        creg[l] = make_float2(c0, c1);
        __nv_bfloat162 h2 = __float22bfloat162_rn(
            make_float2(og.x * tanhf(c0), og.y * tanhf(c1)));
        *(unsigned*)&g_hcat[b * 1024 + l * 512 + o] = *(unsigned*)&h2;
    };

    auto ld_pre0 = [&](int t, float2 (&pre)[2][2]) {
#pragma unroll
        for (int nf = 0; nf < 2; nf++)
#pragma unroll
            for (int r = 0; r < 2; r++)
                pre[nf][r] = __ldcs((const float2*)&g_xw0[
                    ((size_t)t * Bz + eb0 + r * 8) * G4H + encls[nf]]);
    };

    unsigned nb = 0;

    // ---- prologue: L0 step 0 (h = 0 -> gates = xw0[0], no mma) ----
    {
        float2 pre[2][2];
        ld_pre0(0, pre);
        float zero4[2][4] = {};
        gate_epilogue(0, pre, zero4);
    }
    gsync(++nb * NBLK);
    {
        kan_mma_store(0);
        group_sync();
        kan_update(0);
    }
    gsync(++nb * NBLK);

    // ---- main loop: iter i computes L0 step i+1 and L1 step i ----
    for (int i = 0; i < Tt; i++) {
        bool doL0 = (i < Tt - 1);
        // phase A: merged gates (one hcat stream, two weight sets)
        {
            float2 pre0[2][2];
            if (doL0) ld_pre0(i + 1, pre0);
            float a0[2][4] = {}, a1[2][4] = {};
            mma_gates(g_hcat, g_mh * 64, sWg0, sWg1, sAst, a0, a1);
            if (doL0) gate_epilogue(0, pre0, a0);
            float2 pre1[2][2];
#pragma unroll
            for (int nf = 0; nf < 2; nf++) { pre1[nf][0] = pb[nf]; pre1[nf][1] = pb[nf]; }
            gate_epilogue(1, pre1, a1);
        }
        gsync(++nb * NBLK);

        // phase B: both KAN mmas + one group sync + both updates
        {
            if (doL0) {
                kan_mma_store(0);
                __syncthreads();   // staging buffer reuse guard
            }
            kan_mma_store(1);
            group_sync();
            if (doL0) kan_update(0);
            kan_update(1);
        }
        gsync(++nb * NBLK);
    }

    // ---- final FC: out = h1 @ fc_w^T + fc_b ----
    {
        int idx = bid * NTHR + tid;       // 0..32767 == Bz*Oo
        int o = idx >> 7, b = idx & 127;
        float s = fc_b[o];
        const __nv_bfloat16* hp = &g_hcat[b * 1024 + 512];
        const float* wp = &fc_w[(size_t)o * Hh];
#pragma unroll 8
        for (int k = 0; k < Hh; k++) s += __bfloat162float(__ldcg(&hp[k])) * wp[k];
        out[b * Oo + o] = s;
    }
}

// ---------------- launch ----------------
extern "C" void kernel_launch(void* const* d_in, const int* in_sizes, int n_in,
                              void* d_out, int out_size)
{
    const float* x     = (const float*)d_in[0];
    const float* wih   = (const float*)d_in[1];
    const float* whh   = (const float*)d_in[2];
    const float* bih   = (const float*)d_in[3];
    const float* bhh   = (const float*)d_in[4];
    const float* kbase = (const float*)d_in[5];
    const float* kspl  = (const float*)d_in[6];
    const float* kscl  = (const float*)d_in[7];
    const float* grid  = (const float*)d_in[8];
    const float* fc_w  = (const float*)d_in[9];
    const float* fc_b  = (const float*)d_in[10];
    float* out = (float*)d_out;

    cudaFuncSetAttribute(persist_kernel, cudaFuncAttributeMaxDynamicSharedMemorySize, SMEM_TOTAL);

    init_kernel<<<512, NTHR>>>(bih, bhh, grid);
    dim3 gg(G4H / 64, (Tt * Bz) / 128);
    xw0_mma<<<gg, NTHR>>>(x, wih, bih, bhh);
    persist_kernel<<<NBLK, NTHR, SMEM_TOTAL>>>(wih, whh, kbase, kspl, kscl, fc_w, fc_b, out);
}

// round 7
// speedup vs baseline: 7.9907x; 1.0504x over previous
#include <cuda_runtime.h>
#include <cuda_bf16.h>
#include <math.h>

// Problem constants
#define Bz    128
#define Tt    1024
#define Dd    512
#define Hh    512
#define Oo    256
#define G4H   2048
#define FEAT  4608
#define NBLK  128
#define NTHR  256
#define PITCH 48        // tf32 xw0 path smem pitch (floats)

// persist kernel smem layout (bytes)
#define WP_G0 520
#define WP_G1 1032
#define WP_K  584
#define SM_WG0 0
#define SM_WG1 33280
#define SM_WK  99328
#define SM_AST 175104
#define SM_STRIDE 14336
#define SMEM_TOTAL 232448

// ---------------- device scratch ----------------
__device__ float g_xw0[(size_t)Tt * Bz * G4H];   // x@wih0^T + bih0 + bhh0 (fp32)
__device__ float g_bg1[G4H];
__device__ __nv_bfloat16 g_hcat[Bz * 1024];      // [h0 | h1] bf16
__device__ float g_sig[2][Bz * G4H];             // per-layer sigmoided i/f/o
__device__ __nv_bfloat16 g_feat[2][(size_t)Bz * FEAT];
__device__ float g_part[2][8][Bz * Hh];
__device__ float g_kt[12];
__device__ float g_invd[30];
__device__ unsigned g_bar;
__device__ unsigned g_gcnt[16];                  // per-(layer,n-tile) group counters

// ---------------- grid barrier: release/acquire, no L1 flush ----------------
__device__ __forceinline__ void gsync(unsigned target) {
    __syncthreads();
    if (threadIdx.x == 0) {
        asm volatile("red.release.gpu.global.add.u32 [%0], 1;" :: "l"(&g_bar) : "memory");
        unsigned v;
        do {
            asm volatile("ld.acquire.gpu.global.u32 %0, [%1];" : "=r"(v) : "l"(&g_bar) : "memory");
        } while (v < target);
    }
    __syncthreads();
}

// ---------------- bf16 mma primitives ----------------
__device__ __forceinline__ void ldm_x4(unsigned &r0, unsigned &r1, unsigned &r2, unsigned &r3, unsigned addr) {
    asm volatile("ldmatrix.sync.aligned.m8n8.x4.shared.b16 {%0,%1,%2,%3}, [%4];"
                 : "=r"(r0), "=r"(r1), "=r"(r2), "=r"(r3) : "r"(addr));
}
__device__ __forceinline__ void mma16816(float c[4], unsigned a0, unsigned a1, unsigned a2, unsigned a3,
                                         unsigned b0, unsigned b1) {
    asm volatile("mma.sync.aligned.m16n8k16.row.col.f32.bf16.bf16.f32 "
                 "{%0,%1,%2,%3},{%4,%5,%6,%7},{%8,%9},{%0,%1,%2,%3};"
                 : "+f"(c[0]), "+f"(c[1]), "+f"(c[2]), "+f"(c[3])
                 : "r"(a0), "r"(a1), "r"(a2), "r"(a3), "r"(b0), "r"(b1));
}

// ---------------- merged gates mma: one A stream (hcat K=1024), two weight sets ----
__device__ __forceinline__ void mma_gates(
    const __nv_bfloat16* __restrict__ Ag, int arow0,
    const __nv_bfloat16* sWg0, const __nv_bfloat16* sWg1,
    __nv_bfloat16* sA, float (&acc0)[2][4], float (&acc1)[2][4])
{
    constexpr int KCH = 64, AP = 72, NCH = 16;
    int tid = threadIdx.x, lane = tid & 31, warp = tid >> 5;
    int wm = (warp & 3) * 16, wn = (warp >> 2) * 16;
    unsigned sW0a = (unsigned)__cvta_generic_to_shared(sWg0);
    unsigned sW1a = (unsigned)__cvta_generic_to_shared(sWg1);
    unsigned sAa  = (unsigned)__cvta_generic_to_shared(sA);

    auto issue = [&](int cc) {
        const __nv_bfloat16* gb = Ag + (size_t)arow0 * 1024 + cc * KCH;
        unsigned sb = sAa + (cc & 3) * SM_STRIDE;
#pragma unroll
        for (int o = 0; o < 2; o++) {
            int idx = o * NTHR + tid;
            int r = idx >> 3, c = (idx & 7) * 8;
            unsigned sa = sb + (unsigned)(r * AP + c) * 2u;
            const void* ga = gb + (size_t)r * 1024 + c;
            asm volatile("cp.async.cg.shared.global [%0], [%1], 16;" :: "r"(sa), "l"(ga) : "memory");
        }
        asm volatile("cp.async.commit_group;" ::: "memory");
    };
    issue(0); issue(1); issue(2);

    int a_r = (lane & 7) + ((lane >> 3) & 1) * 8;
    int a_k = ((lane >> 4) & 1) * 8;
    int b_r = (lane & 7) + ((lane >> 4) & 1) * 8;
    int b_k = ((lane >> 3) & 1) * 8;
    unsigned b0base = sW0a + (unsigned)((wn + b_r) * WP_G0 + b_k) * 2u;
    unsigned b1base = sW1a + (unsigned)((wn + b_r) * WP_G1 + b_k) * 2u;

    for (int cc = 0; cc < NCH; cc++) {
        asm volatile("cp.async.wait_group 2;" ::: "memory");
        __syncthreads();
        if (cc + 3 < NCH) issue(cc + 3);
        else asm volatile("cp.async.commit_group;" ::: "memory");
        unsigned ab = sAa + (cc & 3) * SM_STRIDE + (unsigned)((wm + a_r) * AP + a_k) * 2u;
#pragma unroll
        for (int ks = 0; ks < 4; ks++) {
            unsigned a0r, a1r, a2r, a3r;
            ldm_x4(a0r, a1r, a2r, a3r, ab + ks * 32);
            unsigned b0, b1, b2, b3;
            ldm_x4(b0, b1, b2, b3, b1base + (unsigned)(cc * KCH + ks * 16) * 2u);
            mma16816(acc1[0], a0r, a1r, a2r, a3r, b0, b1);
            mma16816(acc1[1], a0r, a1r, a2r, a3r, b2, b3);
            if (cc < 8) {
                unsigned c0, c1, c2, c3;
                ldm_x4(c0, c1, c2, c3, b0base + (unsigned)(cc * KCH + ks * 16) * 2u);
                mma16816(acc0[0], a0r, a1r, a2r, a3r, c0, c1);
                mma16816(acc0[1], a0r, a1r, a2r, a3r, c2, c3);
            }
        }
    }
}

// ---------------- KAN mma phase ----------------
template<int MI, int NW, int KCH>
__device__ __forceinline__ void mma_phase(
    const __nv_bfloat16* __restrict__ Ag, int lda, int arow0, int kbeg, int nch,
    const __nv_bfloat16* sW, int wp, __nv_bfloat16* sA, float cacc[MI][NW * 2][4])
{
    constexpr int AP  = KCH + 8;
    constexpr int OPR = KCH / 8;
    constexpr int NOPS = (MI * 64) * KCH / 8 / NTHR;
    int tid = threadIdx.x, lane = tid & 31, warp = tid >> 5;
    int wm = (warp & 3) * (MI * 16), wn = (warp >> 2) * (NW * 16);
    unsigned sWa = (unsigned)__cvta_generic_to_shared(sW);
    unsigned sAa = (unsigned)__cvta_generic_to_shared(sA);

    auto issue = [&](int cc) {
        const __nv_bfloat16* gb = Ag + (size_t)arow0 * lda + kbeg + cc * KCH;
        unsigned sb = sAa + (cc & 3) * SM_STRIDE;
#pragma unroll
        for (int o = 0; o < NOPS; o++) {
            int idx = o * NTHR + tid;
            int r = idx / OPR, c = (idx % OPR) * 8;
            unsigned sa = sb + (unsigned)(r * AP + c) * 2u;
            const void* ga = gb + (size_t)r * lda + c;
            asm volatile("cp.async.cg.shared.global [%0], [%1], 16;" :: "r"(sa), "l"(ga) : "memory");
        }
        asm volatile("cp.async.commit_group;" ::: "memory");
    };

    for (int s = 0; s < 3; s++) {
        if (s < nch) issue(s);
        else asm volatile("cp.async.commit_group;" ::: "memory");
    }

    int a_r = (lane & 7) + ((lane >> 3) & 1) * 8;
    int a_k = ((lane >> 4) & 1) * 8;
    int b_r = (lane & 7) + ((lane >> 4) & 1) * 8;
    int b_k = ((lane >> 3) & 1) * 8;
    unsigned bbase[NW];
#pragma unroll
    for (int nw = 0; nw < NW; nw++)
        bbase[nw] = sWa + (unsigned)((wn + nw * 16 + b_r) * wp + b_k) * 2u;

    for (int cc = 0; cc < nch; cc++) {
        asm volatile("cp.async.wait_group 2;" ::: "memory");
        __syncthreads();
        if (cc + 3 < nch) issue(cc + 3);
        else asm volatile("cp.async.commit_group;" ::: "memory");

        unsigned sb = sAa + (cc & 3) * SM_STRIDE;
        unsigned ab[MI];
#pragma unroll
        for (int mi = 0; mi < MI; mi++)
            ab[mi] = sb + (unsigned)((wm + mi * 16 + a_r) * AP + a_k) * 2u;
#pragma unroll
        for (int ks = 0; ks < KCH / 16; ks++) {
            unsigned a0[MI], a1[MI], a2[MI], a3[MI];
#pragma unroll
            for (int mi = 0; mi < MI; mi++)
                ldm_x4(a0[mi], a1[mi], a2[mi], a3[mi], ab[mi] + ks * 32);
#pragma unroll
            for (int nw = 0; nw < NW; nw++) {
                unsigned b0, b1, b2, b3;
                ldm_x4(b0, b1, b2, b3, bbase[nw] + (unsigned)(cc * KCH + ks * 16) * 2u);
#pragma unroll
                for (int mi = 0; mi < MI; mi++) {
                    mma16816(cacc[mi][nw * 2 + 0], a0[mi], a1[mi], a2[mi], a3[mi], b0, b1);
                    mma16816(cacc[mi][nw * 2 + 1], a0[mi], a1[mi], a2[mi], a3[mi], b2, b3);
                }
            }
        }
    }
}

// ---------------- tiny init ----------------
__global__ void init_kernel(const float* __restrict__ bih, const float* __restrict__ bhh,
                            const float* __restrict__ grid)
{
    size_t stride = (size_t)gridDim.x * blockDim.x;
    size_t t0 = (size_t)blockIdx.x * blockDim.x + threadIdx.x;
    for (size_t i = t0; i < G4H; i += stride) g_bg1[i] = bih[G4H + i] + bhh[G4H + i];
    for (size_t i = t0; i < (size_t)Bz * 1024; i += stride) g_hcat[i] = __float2bfloat16(0.f);
    for (size_t i = t0; i < 12; i += stride) g_kt[i] = grid[i];
    for (size_t i = t0; i < 30; i += stride) {
        int j = (int)i; int k, jj;
        if (j < 11)      { k = 1; jj = j; }
        else if (j < 21) { k = 2; jj = j - 11; }
        else             { k = 3; jj = j - 21; }
        g_invd[i] = 1.0f / (grid[jj + k] - grid[jj]);
    }
    if (t0 < 16) g_gcnt[t0] = 0u;
    if (t0 == 0) g_bar = 0u;
}

// ---------------- tf32 xw0 precompute (unchanged, proven) ----------------
__device__ __forceinline__ unsigned f2tf(float x) {
    unsigned u; asm("cvt.rna.tf32.f32 %0, %1;" : "=r"(u) : "f"(x)); return u;
}
__device__ __forceinline__ void mma8(float c[4], unsigned a0, unsigned a1, unsigned a2, unsigned a3,
                                     unsigned b0, unsigned b1) {
    asm volatile("mma.sync.aligned.m16n8k8.row.col.f32.tf32.tf32.f32 "
                 "{%0,%1,%2,%3},{%4,%5,%6,%7},{%8,%9},{%0,%1,%2,%3};"
                 : "+f"(c[0]), "+f"(c[1]), "+f"(c[2]), "+f"(c[3])
                 : "r"(a0), "r"(a1), "r"(a2), "r"(a3), "r"(b0), "r"(b1));
}
template<int NT>
__device__ __forceinline__ void mma_tile_tf32(const float* __restrict__ A, size_t lda,
                                              const float* __restrict__ W, size_t ldw,
                                              int kbeg, int nch, float* sA, float* sB,
                                              float cacc[2][NT / 16][4])
{
    constexpr int NFR = NT / 16;
    constexpr int BF4 = NT / 32;
    int tid = threadIdx.x, lane = tid & 31, warp = tid >> 5;
    int wm = (warp & 3) * 32, wn = (warp >> 2) * (NT / 2);
    int qr = lane >> 2, qc = lane & 3;
    float4 ra[4], rb[BF4];
    {
        int kb = kbeg;
#pragma unroll
        for (int j = 0; j < 4; j++) { int idx = j * 256 + tid;
            ra[j] = *(const float4*)(A + (size_t)(idx >> 3) * lda + kb + ((idx & 7) << 2)); }
#pragma unroll
        for (int j = 0; j < BF4; j++) { int idx = j * 256 + tid;
            rb[j] = *(const float4*)(W + (size_t)(idx >> 3) * ldw + kb + ((idx & 7) << 2)); }
    }
    for (int cc = 0; cc < nch; cc++) {
        __syncthreads();
#pragma unroll
        for (int j = 0; j < 4; j++) {
            int idx = j * 256 + tid; int row = idx >> 3; int c0 = (idx & 7) << 2;
            int base = row * PITCH + ((c0 >> 4) << 4) + ((c0 & 15) >> 2);
            sA[base + 0]  = __uint_as_float(f2tf(ra[j].x));
            sA[base + 4]  = __uint_as_float(f2tf(ra[j].y));
            sA[base + 8]  = __uint_as_float(f2tf(ra[j].z));
            sA[base + 12] = __uint_as_float(f2tf(ra[j].w));
        }
#pragma unroll
        for (int j = 0; j < BF4; j++) {
            int idx = j * 256 + tid; int row = idx >> 3; int c0 = (idx & 7) << 2;
            int base = row * PITCH + ((c0 >> 4) << 4) + ((c0 & 15) >> 2);
            sB[base + 0]  = __uint_as_float(f2tf(rb[j].x));
            sB[base + 4]  = __uint_as_float(f2tf(rb[j].y));
            sB[base + 8]  = __uint_as_float(f2tf(rb[j].z));
            sB[base + 12] = __uint_as_float(f2tf(rb[j].w));
        }
        __syncthreads();
        if (cc + 1 < nch) {
            int kb = kbeg + (cc + 1) * 32;
#pragma unroll
            for (int j = 0; j < 4; j++) { int idx = j * 256 + tid;
                ra[j] = *(const float4*)(A + (size_t)(idx >> 3) * lda + kb + ((idx & 7) << 2)); }
#pragma unroll
            for (int j = 0; j < BF4; j++) { int idx = j * 256 + tid;
                rb[j] = *(const float4*)(W + (size_t)(idx >> 3) * ldw + kb + ((idx & 7) << 2)); }
        }
#pragma unroll
        for (int h = 0; h < 2; h++) {
            unsigned bf[NFR][4];
#pragma unroll
            for (int f = 0; f < NFR; f++) {
                float4 v = *(const float4*)(sB + (wn + f * 8 + qr) * PITCH + h * 16 + qc * 4);
                bf[f][0] = __float_as_uint(v.x); bf[f][1] = __float_as_uint(v.y);
                bf[f][2] = __float_as_uint(v.z); bf[f][3] = __float_as_uint(v.w);
            }
#pragma unroll
            for (int mi = 0; mi < 2; mi++) {
                float4 lo = *(const float4*)(sA + (wm + mi * 16 + qr) * PITCH + h * 16 + qc * 4);
                float4 hi = *(const float4*)(sA + (wm + mi * 16 + 8 + qr) * PITCH + h * 16 + qc * 4);
#pragma unroll
                for (int f = 0; f < NFR; f++) {
                    mma8(cacc[mi][f], __float_as_uint(lo.x), __float_as_uint(hi.x),
                         __float_as_uint(lo.y), __float_as_uint(hi.y), bf[f][0], bf[f][1]);
                    mma8(cacc[mi][f], __float_as_uint(lo.z), __float_as_uint(hi.z),
                         __float_as_uint(lo.w), __float_as_uint(hi.w), bf[f][2], bf[f][3]);
                }
            }
        }
    }
}

__global__ void __launch_bounds__(NTHR) xw0_mma(const float* __restrict__ x,
                                                const float* __restrict__ wih,
                                                const float* __restrict__ bih,
                                                const float* __restrict__ bhh)
{
    __shared__ __align__(16) float sA[128 * PITCH];
    __shared__ __align__(16) float sB[64 * PITCH];
    int nt = blockIdx.x, mt = blockIdx.y;
    float cacc[2][4][4] = {};
    mma_tile_tf32<64>(x + (size_t)mt * Dd, (size_t)Tt * Dd,
                      wih + (size_t)nt * 64 * Dd, Dd, 0, Dd / 32, sA, sB, cacc);
    int tid = threadIdx.x, lane = tid & 31, warp = tid >> 5;
    int wm = (warp & 3) * 32, wn = (warp >> 2) * 32;
    int qr = lane >> 2, qc = lane & 3;
    size_t rowbase = (size_t)mt * 128;
#pragma unroll
    for (int mi = 0; mi < 2; mi++)
#pragma unroll
        for (int f = 0; f < 4; f++) {
            int r0 = wm + mi * 16 + qr;
            int cb = nt * 64 + wn + f * 8 + qc * 2;
            float b0 = __ldg(&bih[cb]) + __ldg(&bhh[cb]);
            float b1 = __ldg(&bih[cb + 1]) + __ldg(&bhh[cb + 1]);
            *(float2*)(g_xw0 + (rowbase + r0) * G4H + cb) =
                make_float2(cacc[mi][f][0] + b0, cacc[mi][f][1] + b1);
            *(float2*)(g_xw0 + (rowbase + r0 + 8) * G4H + cb) =
                make_float2(cacc[mi][f][2] + b0, cacc[mi][f][3] + b1);
        }
}

// ---------------- persistent sequential kernel (layer-pipelined, split KAN) ----
__global__ void __launch_bounds__(NTHR, 1) persist_kernel(
    const float* __restrict__ wih, const float* __restrict__ whh,
    const float* __restrict__ kbase, const float* __restrict__ kspl,
    const float* __restrict__ kscl, const float* __restrict__ fc_w,
    const float* __restrict__ fc_b, float* __restrict__ out)
{
    extern __shared__ __align__(16) char smem_raw[];
    __nv_bfloat16* sWg0 = (__nv_bfloat16*)(smem_raw + SM_WG0);
    __nv_bfloat16* sWg1 = (__nv_bfloat16*)(smem_raw + SM_WG1);
    __nv_bfloat16* sWk  = (__nv_bfloat16*)(smem_raw + SM_WK);
    __nv_bfloat16* sAst = (__nv_bfloat16*)(smem_raw + SM_AST);

    int bid = blockIdx.x, tid = threadIdx.x;
    int lane = tid & 31, warp = tid >> 5;
    int qr = lane >> 2, qc = lane & 3;
    int g_nt = bid >> 1, g_mh = bid & 1;     // gates: 64 n-tiles(32w) x 2 m-halves
    int lyr  = bid >> 6;                     // KAN layer for this block
    int kb   = bid & 63;
    int k_nt = kb >> 3, k_ks = kb & 7;       // KAN: 8 n-tiles(64w) x 8 k-splits(576)

    // ---- one-time weight preload (gate rows permuted: 8 each of i/f/g/o per tile) ----
    for (int i = tid; i < 32 * 512; i += NTHR) {
        int r = i >> 9, c = i & 511;
        int ng = (r >> 3) * 512 + g_nt * 8 + (r & 7);
        sWg0[r * WP_G0 + c] = __float2bfloat16(whh[(size_t)ng * 512 + c]);
    }
    for (int i = tid; i < 32 * 1024; i += NTHR) {
        int r = i >> 10, c = i & 1023;
        int ng = (r >> 3) * 512 + g_nt * 8 + (r & 7);
        float v = (c < 512) ? wih[(size_t)G4H * Dd + (size_t)ng * 512 + c]
                            : whh[(size_t)G4H * Hh + (size_t)ng * 512 + (c - 512)];
        sWg1[r * WP_G1 + c] = __float2bfloat16(v);
    }
    for (int i = tid; i < 64 * 576; i += NTHR) {
        int r = i / 576, c = i % 576;
        int row = lyr * 512 + k_nt * 64 + r;
        int kk = k_ks * 576 + c;
        float v;
        if (kk < 512) v = kbase[(size_t)row * 512 + kk];
        else {
            int j = kk - 512; int ii = j >> 3, gg = j & 7;
            v = kspl[((size_t)row * 512 + ii) * 8 + gg] * kscl[(size_t)row * 512 + ii];
        }
        sWk[r * WP_K + c] = __float2bfloat16(v);
    }
    __syncthreads();

    float kt[12], invd[30];
#pragma unroll
    for (int q = 0; q < 12; q++) kt[q] = g_kt[q];
#pragma unroll
    for (int q = 0; q < 30; q++) invd[q] = g_invd[q];

    // gates epilogue coordinates (class-permuted columns)
    int wng = (warp >> 2) * 16;
    int eb0 = g_mh * 64 + (warp & 3) * 16 + qr;
    int encls[2]; bool isg[2];
#pragma unroll
    for (int nf = 0; nf < 2; nf++) {
        int cls = (wng + nf * 8) >> 3;
        encls[nf] = cls * 512 + g_nt * 8 + qc * 2;
        isg[nf] = (cls == 2);
    }
    float2 pb[2];
#pragma unroll
    for (int nf = 0; nf < 2; nf++) pb[nf] = *(const float2*)&g_bg1[encls[nf]];

    // fused-update shard (static): 16 rows x 64 cols per block, 2 rows/thread
    int upd_row0 = k_ks * 16 + (tid >> 5);         // +8 for second row
    int upd_col  = k_nt * 64 + ((tid & 31) << 1);
    float2 creg2[2] = {make_float2(0.f, 0.f), make_float2(0.f, 0.f)};
    int gidx = lyr * 8 + k_nt;

    // ---- helpers ----
    auto gate_epilogue = [&](int l, const float2 (&pre)[2][2], const float (&cc4)[2][4]) {
#pragma unroll
        for (int nf = 0; nf < 2; nf++)
#pragma unroll
            for (int r = 0; r < 2; r++) {
                int b = eb0 + r * 8;
                float v0 = cc4[nf][r * 2 + 0] + pre[nf][r].x;
                float v1 = cc4[nf][r * 2 + 1] + pre[nf][r].y;
                if (!isg[nf]) {
                    *(float2*)&g_sig[l][b * G4H + encls[nf]] = make_float2(
                        1.f / (1.f + __expf(-v0)), 1.f / (1.f + __expf(-v1)));
                } else {
#pragma unroll
                    for (int e = 0; e < 2; e++) {
                        float v = e ? v1 : v0;
                        int ii = encls[nf] + e - 1024;
                        g_feat[l][(size_t)b * FEAT + ii] =
                            __float2bfloat16(v / (1.f + __expf(-v)));
                        float bas[11];
#pragma unroll
                        for (int q = 0; q < 11; q++)
                            bas[q] = (v >= kt[q] && v < kt[q + 1]) ? 1.f : 0.f;
#pragma unroll
                        for (int k = 1; k <= 3; k++) {
                            int off = (k == 1) ? 0 : ((k == 2) ? 11 : 21);
#pragma unroll
                            for (int q = 0; q + k < 11; q++) {
                                float lf = (v - kt[q]) * invd[off + q];
                                float rf = (kt[q + k + 1] - v) * invd[off + q + 1];
                                bas[q] = lf * bas[q] + rf * bas[q + 1];
                            }
                        }
                        __nv_bfloat162 p0 = __float22bfloat162_rn(make_float2(bas[0], bas[1]));
                        __nv_bfloat162 p1 = __float22bfloat162_rn(make_float2(bas[2], bas[3]));
                        __nv_bfloat162 p2 = __float22bfloat162_rn(make_float2(bas[4], bas[5]));
                        __nv_bfloat162 p3 = __float22bfloat162_rn(make_float2(bas[6], bas[7]));
                        uint4 u;
                        u.x = *(unsigned*)&p0; u.y = *(unsigned*)&p1;
                        u.z = *(unsigned*)&p2; u.w = *(unsigned*)&p3;
                        *(uint4*)&g_feat[l][(size_t)b * FEAT + Hh + ii * 8] = u;
                    }
                }
            }
    };

    unsigned gs = 0;
    // full KAN step for this block's layer: mma (K=576, 12 chunks) + group sync + update
    auto kan_step = [&](void) {
        int l = lyr;
        float cacc[2][4][4] = {};
        mma_phase<2, 2, 48>(g_feat[l], FEAT, 0, k_ks * 576, 12, sWk, WP_K, sAst, cacc);
        int wm = (warp & 3) * 32, wn = (warp >> 2) * 32;
#pragma unroll
        for (int mi = 0; mi < 2; mi++)
#pragma unroll
            for (int f = 0; f < 4; f++) {
                int r0 = wm + mi * 16 + qr;
                int cb = k_nt * 64 + wn + (f >> 1) * 16 + (f & 1) * 8 + qc * 2;
                *(float2*)&g_part[l][k_ks][r0 * Hh + cb] =
                    make_float2(cacc[mi][f][0], cacc[mi][f][1]);
                *(float2*)&g_part[l][k_ks][(r0 + 8) * Hh + cb] =
                    make_float2(cacc[mi][f][2], cacc[mi][f][3]);
            }

        // prefetch sigmoid operands (published at the phase-A gsync -> safe now)
        float2 ig[2], fg[2], og[2];
#pragma unroll
        for (int r = 0; r < 2; r++) {
            int b = upd_row0 + r * 8, o = upd_col;
            ig[r] = __ldcg((const float2*)&g_sig[l][b * G4H + o]);
            fg[r] = __ldcg((const float2*)&g_sig[l][b * G4H + 512 + o]);
            og[r] = __ldcg((const float2*)&g_sig[l][b * G4H + 1536 + o]);
        }

        // group sync: 8 k-split siblings of this (layer, n-tile)
        ++gs;
        __syncthreads();
        if (tid == 0) {
            asm volatile("red.release.gpu.global.add.u32 [%0], 1;"
                         :: "l"(&g_gcnt[gidx]) : "memory");
            unsigned v, tgt = gs * 8;
            do {
                asm volatile("ld.acquire.gpu.global.u32 %0, [%1];"
                             : "=r"(v) : "l"(&g_gcnt[gidx]) : "memory");
            } while (v < tgt);
        }
        __syncthreads();

        // update this block's static shard (c in registers)
#pragma unroll
        for (int r = 0; r < 2; r++) {
            int b = upd_row0 + r * 8, o = upd_col;
            float2 v = make_float2(0.f, 0.f);
#pragma unroll
            for (int s = 0; s < 8; s++) {
                float2 p = __ldcg((const float2*)&g_part[l][s][b * Hh + o]);
                v.x += p.x; v.y += p.y;
            }
            float c0 = fg[r].x * creg2[r].x + ig[r].x * v.x;
            float c1 = fg[r].y * creg2[r].y + ig[r].y * v.y;
            creg2[r] = make_float2(c0, c1);
            __nv_bfloat162 h2 = __float22bfloat162_rn(
                make_float2(og[r].x * tanhf(c0), og[r].y * tanhf(c1)));
            *(unsigned*)&g_hcat[b * 1024 + l * 512 + o] = *(unsigned*)&h2;
        }
    };

    auto ld_pre0 = [&](int t, float2 (&pre)[2][2]) {
#pragma unroll
        for (int nf = 0; nf < 2; nf++)
#pragma unroll
            for (int r = 0; r < 2; r++)
                pre[nf][r] = __ldcs((const float2*)&g_xw0[
                    ((size_t)t * Bz + eb0 + r * 8) * G4H + encls[nf]]);
    };

    unsigned nb = 0;

    // ---- prologue: L0 step 0 (h = 0 -> gates = xw0[0], no mma) ----
    {
        float2 pre[2][2];
        ld_pre0(0, pre);
        float zero4[2][4] = {};
        gate_epilogue(0, pre, zero4);
    }
    gsync(++nb * NBLK);
    if (lyr == 0) kan_step();
    gsync(++nb * NBLK);

    // ---- main loop: iter i -> L0 step i+1 (blocks 0-63) and L1 step i (64-127) ----
    for (int i = 0; i < Tt; i++) {
        bool doL0 = (i < Tt - 1);
        // phase A: merged gates (one hcat stream, two weight sets)
        {
            float2 pre0[2][2];
            if (doL0) ld_pre0(i + 1, pre0);
            float a0[2][4] = {}, a1[2][4] = {};
            mma_gates(g_hcat, g_mh * 64, sWg0, sWg1, sAst, a0, a1);
            if (doL0) gate_epilogue(0, pre0, a0);
            float2 pre1[2][2];
#pragma unroll
            for (int nf = 0; nf < 2; nf++) { pre1[nf][0] = pb[nf]; pre1[nf][1] = pb[nf]; }
            gate_epilogue(1, pre1, a1);
        }
        gsync(++nb * NBLK);

        // phase B: this block's layer KAN (L0 blocks process step i+1, L1 step i)
        if (lyr == 1 || doL0) kan_step();
        gsync(++nb * NBLK);
    }

    // ---- final FC: out = h1 @ fc_w^T + fc_b ----
    {
        int idx = bid * NTHR + tid;       // 0..32767 == Bz*Oo
        int o = idx >> 7, b = idx & 127;
        float s = fc_b[o];
        const __nv_bfloat16* hp = &g_hcat[b * 1024 + 512];
        const float* wp = &fc_w[(size_t)o * Hh];
#pragma unroll 8
        for (int k = 0; k < Hh; k++) s += __bfloat162float(__ldcg(&hp[k])) * wp[k];
        out[b * Oo + o] = s;
    }
}

// ---------------- launch ----------------
extern "C" void kernel_launch(void* const* d_in, const int* in_sizes, int n_in,
                              void* d_out, int out_size)
{
    const float* x     = (const float*)d_in[0];
    const float* wih   = (const float*)d_in[1];
    const float* whh   = (const float*)d_in[2];
    const float* bih   = (const float*)d_in[3];
    const float* bhh   = (const float*)d_in[4];
    const float* kbase = (const float*)d_in[5];
    const float* kspl  = (const float*)d_in[6];
    const float* kscl  = (const float*)d_in[7];
    const float* grid  = (const float*)d_in[8];
    const float* fc_w  = (const float*)d_in[9];
    const float* fc_b  = (const float*)d_in[10];
    float* out = (float*)d_out;

    cudaFuncSetAttribute(persist_kernel, cudaFuncAttributeMaxDynamicSharedMemorySize, SMEM_TOTAL);

    init_kernel<<<512, NTHR>>>(bih, bhh, grid);
    dim3 gg(G4H / 64, (Tt * Bz) / 128);
    xw0_mma<<<gg, NTHR>>>(x, wih, bih, bhh);
    persist_kernel<<<NBLK, NTHR, SMEM_TOTAL>>>(wih, whh, kbase, kspl, kscl, fc_w, fc_b, out);
}